// round 15
// baseline (speedup 1.0000x reference)
#include <cuda_runtime.h>
#include <cuda_bf16.h>
#include <cstdint>
#include <math.h>

// Problem constants
#define BATCH 4
#define S_LEN 2048
#define DMODEL 768
#define NHEAD 12
#define HDIM 64
#define NTOK (BATCH * S_LEN)            // 8192
#define MASK_N (NHEAD * S_LEN * S_LEN)  // 50331648

#define LOG2E 1.4426950408889634f

// -------------------- scratch (__device__ globals) -------------------------
__device__ __nv_bfloat16 g_hh[NTOK * DMODEL];
__device__ __nv_bfloat16 g_hl[NTOK * DMODEL];
__device__ __nv_bfloat16 g_wh[4][DMODEL * DMODEL];
__device__ __nv_bfloat16 g_wl[4][DMODEL * DMODEL];
__device__ __nv_bfloat16 g_qh[BATCH * NHEAD * S_LEN * HDIM];  // [b,h,s,d]
__device__ __nv_bfloat16 g_ql[BATCH * NHEAD * S_LEN * HDIM];
__device__ __nv_bfloat16 g_kh[BATCH * NHEAD * S_LEN * HDIM];
__device__ __nv_bfloat16 g_kl[BATCH * NHEAD * S_LEN * HDIM];
__device__ __nv_bfloat16 g_vh[BATCH * NHEAD * HDIM * S_LEN];  // [b,h,d,s]
__device__ __nv_bfloat16 g_vl[BATCH * NHEAD * HDIM * S_LEN];
__device__ __nv_bfloat16 g_ch[NTOK * DMODEL];
__device__ __nv_bfloat16 g_cl[NTOK * DMODEL];
__device__ unsigned g_maskbits[MASK_N / 32];
__device__ int g_mask_mode;

// ---------------------------------------------------------------------------
// cp.async / smem helpers
// ---------------------------------------------------------------------------
__device__ __forceinline__ unsigned smem_u32(const void* p)
{
    return (unsigned)__cvta_generic_to_shared(p);
}
__device__ __forceinline__ void cp16(void* s, const void* g)
{
    asm volatile("cp.async.cg.shared.global [%0], [%1], 16;"
                 :: "r"(smem_u32(s)), "l"(g));
}
__device__ __forceinline__ void cp4(void* s, const void* g)
{
    asm volatile("cp.async.ca.shared.global [%0], [%1], 4;"
                 :: "r"(smem_u32(s)), "l"(g));
}
#define CP_COMMIT() asm volatile("cp.async.commit_group;")
#define CP_WAIT0()  asm volatile("cp.async.wait_group 0;")
#define CP_WAIT1()  asm volatile("cp.async.wait_group 1;")

// ldmatrix x4
__device__ __forceinline__ void ldsm_x4(unsigned* r, unsigned addr)
{
    asm volatile("ldmatrix.sync.aligned.m8n8.x4.shared.b16 {%0,%1,%2,%3}, [%4];"
                 : "=r"(r[0]), "=r"(r[1]), "=r"(r[2]), "=r"(r[3]) : "r"(addr));
}

// nonzero -> 1 bit (any-bit-set via sign trick)
__device__ __forceinline__ unsigned nz_bit(int x)
{
    return ((unsigned)(x | -x)) >> 31;
}

// ---------------------------------------------------------------------------
// Mask dtype detection (proven R4-R14)
// ---------------------------------------------------------------------------
__global__ void detect_mask_kernel(const unsigned char* __restrict__ m)
{
    __shared__ unsigned cnt[4];
    if (threadIdx.x < 4) cnt[threadIdx.x] = 0;
    __syncthreads();
    for (int i = threadIdx.x; i < 8192; i += blockDim.x)
        if (m[i]) atomicAdd(&cnt[i & 3], 1u);
    __syncthreads();
    if (threadIdx.x == 0) {
        int mode;
        if (cnt[1] + cnt[2] + cnt[3] == 0) mode = 1;   // int32 0/1
        else if (cnt[0] > 0)               mode = 0;   // uint8
        else                               mode = 2;   // float32
        g_mask_mode = mode;
    }
}

// Mask -> bitmask; each thread packs 32 consecutive elements.
__global__ void __launch_bounds__(256)
convert_maskbits_kernel(const void* __restrict__ mraw, unsigned* __restrict__ out)
{
    const int mode = g_mask_mode;
    const size_t t = (size_t)blockIdx.x * blockDim.x + threadIdx.x;
    if (t >= MASK_N / 32) return;
    unsigned w = 0;
    if (mode == 1) {
        const int4* p = (const int4*)mraw + t * 8;
#pragma unroll
        for (int i = 0; i < 8; i++) {
            int4 v = p[i];
            w |= nz_bit(v.x) << (i * 4);
            w |= nz_bit(v.y) << (i * 4 + 1);
            w |= nz_bit(v.z) << (i * 4 + 2);
            w |= nz_bit(v.w) << (i * 4 + 3);
        }
    } else if (mode == 0) {
        const uint4* p = (const uint4*)mraw + t * 2;
#pragma unroll
        for (int i = 0; i < 2; i++) {
            uint4 v = p[i];
            unsigned words[4] = { v.x, v.y, v.z, v.w };
#pragma unroll
            for (int j = 0; j < 4; j++)
#pragma unroll
                for (int bb = 0; bb < 4; bb++)
                    w |= (((words[j] >> (bb * 8)) & 0xFFu) ? 1u : 0u)
                         << (i * 16 + j * 4 + bb);
        }
    } else {
        const int4* p = (const int4*)mraw + t * 8;   // fp32 bits: nonzero test ok
#pragma unroll
        for (int i = 0; i < 8; i++) {
            int4 v = p[i];
            w |= nz_bit(v.x) << (i * 4);
            w |= nz_bit(v.y) << (i * 4 + 1);
            w |= nz_bit(v.z) << (i * 4 + 2);
            w |= nz_bit(v.w) << (i * 4 + 3);
        }
    }
    out[t] = w;
}

// ---------------------------------------------------------------------------
// fp32 -> bf16 hi/lo split
// ---------------------------------------------------------------------------
__device__ __forceinline__ unsigned pack_bf16x2(float x, float y)
{
    __nv_bfloat162 t = __float22bfloat162_rn(make_float2(x, y));
    return *(unsigned*)&t;
}

__device__ __forceinline__ void split_hilo2(float x, float y, unsigned& hi, unsigned& lo)
{
    hi = pack_bf16x2(x, y);
    float hx = __uint_as_float(hi << 16);
    float hy = __uint_as_float(hi & 0xffff0000u);
    lo = pack_bf16x2(x - hx, y - hy);
}

// Fused: convert hidden (y==4) + all 4 weights (y==0..3)
__global__ void __launch_bounds__(256)
cvt_all_kernel(const float* __restrict__ hid,
               const float* __restrict__ w0, const float* __restrict__ w1,
               const float* __restrict__ w2, const float* __restrict__ w3,
               __nv_bfloat16* __restrict__ HH, __nv_bfloat16* __restrict__ HL,
               __nv_bfloat16* __restrict__ WH, __nv_bfloat16* __restrict__ WL)
{
    const int y = blockIdx.y;
    const int i = blockIdx.x * blockDim.x + threadIdx.x;
    const float* x;
    __nv_bfloat16 *h, *l;
    int n4;
    if (y == 4) {
        n4 = NTOK * DMODEL / 4;
        x = hid; h = HH; l = HL;
    } else {
        n4 = DMODEL * DMODEL / 4;
        x = (y == 0) ? w0 : (y == 1) ? w1 : (y == 2) ? w2 : w3;
        h = WH + (size_t)y * DMODEL * DMODEL;
        l = WL + (size_t)y * DMODEL * DMODEL;
    }
    if (i >= n4) return;
    float4 v = ((const float4*)x)[i];
    uint2 ph, pl;
    split_hilo2(v.x, v.y, ph.x, pl.x);
    split_hilo2(v.z, v.w, ph.y, pl.y);
    ((uint2*)h)[i] = ph;
    ((uint2*)l)[i] = pl;
}

// ---------------------------------------------------------------------------
// mma.sync m16n8k16 bf16 (f32 accumulate)
// ---------------------------------------------------------------------------
__device__ __forceinline__ void mma_bf16(float* c, const unsigned* a, const unsigned* b)
{
    asm volatile(
        "mma.sync.aligned.m16n8k16.row.col.f32.bf16.bf16.f32 "
        "{%0,%1,%2,%3},{%4,%5,%6,%7},{%8,%9},{%0,%1,%2,%3};"
        : "+f"(c[0]), "+f"(c[1]), "+f"(c[2]), "+f"(c[3])
        : "r"(a[0]), "r"(a[1]), "r"(a[2]), "r"(a[3]),
          "r"(b[0]), "r"(b[1]));
}

// ---------------------------------------------------------------------------
// GEMM core (unchanged from R12 — at ~95% of mma.sync cap)
// ---------------------------------------------------------------------------
struct GemmSmem {
    __nv_bfloat16 Ahs[128][40];
    __nv_bfloat16 Als[128][40];
    __nv_bfloat16 Whs[128][40];
    __nv_bfloat16 Wls[128][40];
};
#define GEMM_SMEM_BYTES (2 * sizeof(GemmSmem))

__device__ __forceinline__ void gemm_load_stage(
    GemmSmem& sm, const __nv_bfloat16* __restrict__ Ah, const __nv_bfloat16* __restrict__ Al,
    const __nv_bfloat16* __restrict__ Wh, const __nv_bfloat16* __restrict__ Wl,
    int bm, int bn, int k0, int tid)
{
#pragma unroll
    for (int it = 0; it < 2; it++) {
        int fid = tid + it * 256;
        int row = fid >> 2, cc = (fid & 3) * 8;
        cp16(&sm.Ahs[row][cc], &Ah[(size_t)(bm + row) * DMODEL + k0 + cc]);
        cp16(&sm.Als[row][cc], &Al[(size_t)(bm + row) * DMODEL + k0 + cc]);
        cp16(&sm.Whs[row][cc], &Wh[(size_t)(bn + row) * DMODEL + k0 + cc]);
        cp16(&sm.Wls[row][cc], &Wl[(size_t)(bn + row) * DMODEL + k0 + cc]);
    }
}

__device__ __forceinline__ void gemm_tile(
    GemmSmem* bufs, const __nv_bfloat16* __restrict__ Ah, const __nv_bfloat16* __restrict__ Al,
    const __nv_bfloat16* __restrict__ Wh, const __nv_bfloat16* __restrict__ Wl,
    int bm, int bn, float c[16][4])
{
    const int tid  = threadIdx.x;
    const int lane = tid & 31;
    const int w    = tid >> 5;
    const int wm   = w >> 2;
    const int wn   = w & 3;
    const int NKT  = DMODEL / 32;   // 24

    const unsigned lbA = (unsigned)(((lane & 7) + ((lane >> 3) & 1) * 8) * 80
                                    + ((lane >> 4) & 1) * 16);
    const unsigned lbB = (unsigned)(((lane & 7) + ((lane >> 4) & 1) * 8) * 80
                                    + ((lane >> 3) & 1) * 16);

#pragma unroll
    for (int i = 0; i < 16; i++)
#pragma unroll
        for (int j = 0; j < 4; j++) c[i][j] = 0.f;

    gemm_load_stage(bufs[0], Ah, Al, Wh, Wl, bm, bn, 0, tid);
    CP_COMMIT();

    for (int kt = 0; kt < NKT; kt++) {
        if (kt + 1 < NKT) {
            gemm_load_stage(bufs[(kt + 1) & 1], Ah, Al, Wh, Wl, bm, bn, (kt + 1) * 32, tid);
            CP_COMMIT();
            CP_WAIT1();
        } else {
            CP_WAIT0();
        }
        __syncthreads();
        GemmSmem& sm = bufs[kt & 1];
        const unsigned ahb = smem_u32(&sm.Ahs[0][0]) + (wm * 64) * 80 + lbA;
        const unsigned alb = smem_u32(&sm.Als[0][0]) + (wm * 64) * 80 + lbA;
        const unsigned whb = smem_u32(&sm.Whs[0][0]) + (wn * 32) * 80 + lbB;
        const unsigned wlb = smem_u32(&sm.Wls[0][0]) + (wn * 32) * 80 + lbB;

#pragma unroll
        for (int kf = 0; kf < 2; kf++) {
            unsigned ah[4][4], al[4][4];
#pragma unroll
            for (int mf = 0; mf < 4; mf++) {
                ldsm_x4(ah[mf], ahb + mf * (16 * 80) + kf * 32);
                ldsm_x4(al[mf], alb + mf * (16 * 80) + kf * 32);
            }
            unsigned wh_[2][4], wl_[2][4];
#pragma unroll
            for (int p = 0; p < 2; p++) {
                ldsm_x4(wh_[p], whb + p * (16 * 80) + kf * 32);
                ldsm_x4(wl_[p], wlb + p * (16 * 80) + kf * 32);
            }
#pragma unroll
            for (int mf = 0; mf < 4; mf++)
#pragma unroll
                for (int nf = 0; nf < 4; nf++) {
                    const unsigned* bh = &wh_[nf >> 1][(nf & 1) * 2];
                    const unsigned* bl = &wl_[nf >> 1][(nf & 1) * 2];
                    mma_bf16(c[mf * 4 + nf], ah[mf], bh);
                    mma_bf16(c[mf * 4 + nf], ah[mf], bl);
                    mma_bf16(c[mf * 4 + nf], al[mf], bh);
                }
        }
        __syncthreads();
    }
}

// ---------------------------------------------------------------------------
// Fused QKV projection: grid.z = 0(Q),1(K),2(V). Q pre-scaled by 0.125*log2(e).
// ---------------------------------------------------------------------------
__global__ void __launch_bounds__(256)
qkv_gemm_kernel(const __nv_bfloat16* __restrict__ Ah, const __nv_bfloat16* __restrict__ Al,
                const __nv_bfloat16* __restrict__ WhB, const __nv_bfloat16* __restrict__ WlB,
                const float* __restrict__ bq, const float* __restrict__ bk,
                const float* __restrict__ bv,
                __nv_bfloat16* __restrict__ QH, __nv_bfloat16* __restrict__ QL,
                __nv_bfloat16* __restrict__ KH, __nv_bfloat16* __restrict__ KL,
                __nv_bfloat16* __restrict__ VH, __nv_bfloat16* __restrict__ VL)
{
    extern __shared__ char smem_raw[];
    GemmSmem* bufs = (GemmSmem*)smem_raw;

    const int z = blockIdx.z;
    const __nv_bfloat16* Wh = WhB + (size_t)z * DMODEL * DMODEL;
    const __nv_bfloat16* Wl = WlB + (size_t)z * DMODEL * DMODEL;
    const float* bias = (z == 0) ? bq : (z == 1) ? bk : bv;
    const float scale = (z == 0) ? (0.125f * LOG2E) : 1.0f;
    __nv_bfloat16* CH = (z == 0) ? QH : (z == 1) ? KH : VH;
    __nv_bfloat16* CL = (z == 0) ? QL : (z == 1) ? KL : VL;

    const int bm = blockIdx.y * 128;
    const int bn = blockIdx.x * 128;
    float c[16][4];
    gemm_tile(bufs, Ah, Al, Wh, Wl, bm, bn, c);

    const int tid  = threadIdx.x;
    const int lane = tid & 31;
    const int w    = tid >> 5;
    const int g    = lane >> 2;
    const int t2   = (lane & 3) * 2;
    const int wm   = w >> 2;
    const int wn   = w & 3;

#pragma unroll
    for (int mf = 0; mf < 4; mf++) {
#pragma unroll
        for (int nf = 0; nf < 4; nf++) {
            const int colb = bn + wn * 32 + nf * 8 + t2;
            const float b0 = bias[colb], b1 = bias[colb + 1];
            float v[4] = { (c[mf * 4 + nf][0] + b0) * scale, (c[mf * 4 + nf][1] + b1) * scale,
                           (c[mf * 4 + nf][2] + b0) * scale, (c[mf * 4 + nf][3] + b1) * scale };
#pragma unroll
            for (int half = 0; half < 2; half++) {
                const int m = bm + wm * 64 + mf * 16 + g + half * 8;
                const float x0 = v[half * 2], x1 = v[half * 2 + 1];
                const int b = m >> 11;
                const int s = m & 2047;
                const int h = colb >> 6;
                const int d = colb & 63;
                if (z != 2) {
                    unsigned hi, lo;
                    split_hilo2(x0, x1, hi, lo);
                    size_t idx = (((size_t)b * NHEAD + h) * S_LEN + s) * HDIM + d;
                    *(unsigned*)&CH[idx] = hi;
                    *(unsigned*)&CL[idx] = lo;
                } else {
                    float h0 = __bfloat162float(__float2bfloat16(x0));
                    float h1 = __bfloat162float(__float2bfloat16(x1));
                    size_t base = (((size_t)b * NHEAD + h) * HDIM + d) * S_LEN + s;
                    CH[base] = __float2bfloat16(h0);
                    CL[base] = __float2bfloat16(x0 - h0);
                    CH[base + S_LEN] = __float2bfloat16(h1);
                    CL[base + S_LEN] = __float2bfloat16(x1 - h1);
                }
            }
        }
    }
}

// ---------------------------------------------------------------------------
// Output projection: plain fp32 [m,n]
// ---------------------------------------------------------------------------
__global__ void __launch_bounds__(256)
out_gemm_kernel(const __nv_bfloat16* __restrict__ Ah, const __nv_bfloat16* __restrict__ Al,
                const __nv_bfloat16* __restrict__ Wh, const __nv_bfloat16* __restrict__ Wl,
                const float* __restrict__ bias, float* __restrict__ Cf)
{
    extern __shared__ char smem_raw[];
    GemmSmem* bufs = (GemmSmem*)smem_raw;

    const int bm = blockIdx.y * 128;
    const int bn = blockIdx.x * 128;
    float c[16][4];
    gemm_tile(bufs, Ah, Al, Wh, Wl, bm, bn, c);

    const int tid  = threadIdx.x;
    const int lane = tid & 31;
    const int w    = tid >> 5;
    const int g    = lane >> 2;
    const int t2   = (lane & 3) * 2;
    const int wm   = w >> 2;
    const int wn   = w & 3;

#pragma unroll
    for (int mf = 0; mf < 4; mf++)
#pragma unroll
        for (int nf = 0; nf < 4; nf++) {
            const int colb = bn + wn * 32 + nf * 8 + t2;
            const float b0 = bias[colb], b1 = bias[colb + 1];
#pragma unroll
            for (int half = 0; half < 2; half++) {
                const int m = bm + wm * 64 + mf * 16 + g + half * 8;
                float2 p = { c[mf * 4 + nf][half * 2] + b0,
                             c[mf * 4 + nf][half * 2 + 1] + b1 };
                *(float2*)&Cf[(size_t)m * DMODEL + colb] = p;
            }
        }
}

#define MASKVAL (-1e30f)

// ---------------------------------------------------------------------------
// Flash attention (R14 core): 32 q-rows per warp, 32-key tiles, exp2.
// ---------------------------------------------------------------------------
#define KT_KEYS 32
struct FlashSmem {
    __nv_bfloat16 kh[KT_KEYS][72];
    __nv_bfloat16 kl[KT_KEYS][72];
    __nv_bfloat16 vh[64][40];
    __nv_bfloat16 vl[64][40];
    unsigned m32[128];
};
#define FLASH_SMEM_BYTES (2 * sizeof(FlashSmem))

__global__ void __launch_bounds__(128)
flash_mma_kernel(const __nv_bfloat16* __restrict__ qh, const __nv_bfloat16* __restrict__ ql,
                 const __nv_bfloat16* __restrict__ kh, const __nv_bfloat16* __restrict__ kl,
                 const __nv_bfloat16* __restrict__ vh, const __nv_bfloat16* __restrict__ vl,
                 const unsigned* __restrict__ mbits,
                 __nv_bfloat16* __restrict__ ch, __nv_bfloat16* __restrict__ cl)
{
    extern __shared__ char smem_raw[];
    FlashSmem* bufs = (FlashSmem*)smem_raw;

    const int tid  = threadIdx.x;
    const int w    = tid >> 5;
    const int lane = tid & 31;
    const int g    = lane >> 2;
    const int t2   = (lane & 3) * 2;
    const int qt = blockIdx.x, h = blockIdx.y, b = blockIdx.z;
    const int qbase = qt * 128;
    const int wq = w * 32;

    const size_t bh   = (size_t)(b * NHEAD + h);
    const size_t kvb  = bh * S_LEN * HDIM;
    const size_t vtb  = bh * HDIM * S_LEN;
    const size_t mb32 = ((size_t)h * S_LEN + qbase) * (S_LEN / 32);
    const int NT = S_LEN / KT_KEYS;   // 64

    const unsigned lbK = (unsigned)(((lane & 7) + ((lane >> 4) & 1) * 8) * 144
                                    + ((lane >> 3) & 1) * 16);
    const unsigned lbV = (unsigned)(((lane & 7) + ((lane >> 4) & 1) * 8) * 80
                                    + ((lane >> 3) & 1) * 16);

    auto load_stage = [&](int buf, int kt) {
        FlashSmem& sm = bufs[buf];
#pragma unroll
        for (int it = 0; it < 2; it++) {
            int fid = tid + it * 128;
            int krow = fid >> 3, kcc = (fid & 7) * 8;
            cp16(&sm.kh[krow][kcc], &kh[kvb + (size_t)(kt * KT_KEYS + krow) * HDIM + kcc]);
            cp16(&sm.kl[krow][kcc], &kl[kvb + (size_t)(kt * KT_KEYS + krow) * HDIM + kcc]);
            int vrow = fid >> 2, vcc = (fid & 3) * 8;
            cp16(&sm.vh[vrow][vcc], &vh[vtb + (size_t)vrow * S_LEN + kt * KT_KEYS + vcc]);
            cp16(&sm.vl[vrow][vcc], &vl[vtb + (size_t)vrow * S_LEN + kt * KT_KEYS + vcc]);
        }
        cp4(&sm.m32[tid], &mbits[mb32 + (size_t)tid * (S_LEN / 32) + kt]);
    };

    unsigned qfh[2][4][4], qfl[2][4][4];
#pragma unroll
    for (int mf = 0; mf < 2; mf++) {
        const size_t r0 = (size_t)(qbase + wq + mf * 16 + g) * HDIM;
        const size_t r1 = r0 + 8 * HDIM;
        const __nv_bfloat16* ph = qh + kvb;
        const __nv_bfloat16* pl = ql + kvb;
#pragma unroll
        for (int kf = 0; kf < 4; kf++) {
            int c0 = kf * 16 + t2, c1 = c0 + 8;
            qfh[mf][kf][0] = *(const unsigned*)&ph[r0 + c0];
            qfh[mf][kf][1] = *(const unsigned*)&ph[r1 + c0];
            qfh[mf][kf][2] = *(const unsigned*)&ph[r0 + c1];
            qfh[mf][kf][3] = *(const unsigned*)&ph[r1 + c1];
            qfl[mf][kf][0] = *(const unsigned*)&pl[r0 + c0];
            qfl[mf][kf][1] = *(const unsigned*)&pl[r1 + c0];
            qfl[mf][kf][2] = *(const unsigned*)&pl[r0 + c1];
            qfl[mf][kf][3] = *(const unsigned*)&pl[r1 + c1];
        }
    }

    float o[2][8][4];
#pragma unroll
    for (int mf = 0; mf < 2; mf++)
#pragma unroll
        for (int dt = 0; dt < 8; dt++)
#pragma unroll
            for (int i = 0; i < 4; i++) o[mf][dt][i] = 0.f;
    float lsum[2][2] = { {0.f, 0.f}, {0.f, 0.f} };

    load_stage(0, 0);
    CP_COMMIT();

    for (int kt = 0; kt < NT; kt++) {
        if (kt + 1 < NT) {
            load_stage((kt + 1) & 1, kt + 1);
            CP_COMMIT();
            CP_WAIT1();
        } else {
            CP_WAIT0();
        }
        __syncthreads();
        FlashSmem& sm = bufs[kt & 1];
        const unsigned khb = smem_u32(&sm.kh[0][0]) + lbK;
        const unsigned klb = smem_u32(&sm.kl[0][0]) + lbK;
        const unsigned vhb = smem_u32(&sm.vh[0][0]) + lbV;
        const unsigned vlb = smem_u32(&sm.vl[0][0]) + lbV;

        float sacc[2][4][4];
#pragma unroll
        for (int mf = 0; mf < 2; mf++)
#pragma unroll
            for (int nt = 0; nt < 4; nt++)
#pragma unroll
                for (int i = 0; i < 4; i++) sacc[mf][nt][i] = 0.f;

#pragma unroll
        for (int kf = 0; kf < 4; kf++) {
#pragma unroll
            for (int p = 0; p < 2; p++) {
                unsigned bh4[4], bl4[4];
                ldsm_x4(bh4, khb + p * (16 * 144) + kf * 32);
                ldsm_x4(bl4, klb + p * (16 * 144) + kf * 32);
#pragma unroll
                for (int mf = 0; mf < 2; mf++) {
                    mma_bf16(sacc[mf][2 * p],     qfh[mf][kf], bh4 + 0);
                    mma_bf16(sacc[mf][2 * p],     qfh[mf][kf], bl4 + 0);
                    mma_bf16(sacc[mf][2 * p],     qfl[mf][kf], bh4 + 0);
                    mma_bf16(sacc[mf][2 * p + 1], qfh[mf][kf], bh4 + 2);
                    mma_bf16(sacc[mf][2 * p + 1], qfh[mf][kf], bl4 + 2);
                    mma_bf16(sacc[mf][2 * p + 1], qfl[mf][kf], bh4 + 2);
                }
            }
        }

        unsigned pfh[2][4][2], pfl[2][4][2];
#pragma unroll
        for (int mf = 0; mf < 2; mf++) {
            const unsigned w0 = sm.m32[wq + mf * 16 + g] >> t2;
            const unsigned w1 = sm.m32[wq + mf * 16 + 8 + g] >> t2;
#pragma unroll
            for (int nt = 0; nt < 4; nt++) {
                unsigned b0 = w0 >> (nt * 8);
                unsigned b1 = w1 >> (nt * 8);
                float s0 = (b0 & 1u) ? sacc[mf][nt][0] : MASKVAL;
                float s1 = (b0 & 2u) ? sacc[mf][nt][1] : MASKVAL;
                float s2 = (b1 & 1u) ? sacc[mf][nt][2] : MASKVAL;
                float s3 = (b1 & 2u) ? sacc[mf][nt][3] : MASKVAL;
                float p0 = exp2f(s0);
                float p1 = exp2f(s1);
                float p2 = exp2f(s2);
                float p3 = exp2f(s3);
                lsum[mf][0] += p0 + p1;
                lsum[mf][1] += p2 + p3;
                split_hilo2(p0, p1, pfh[mf][nt][0], pfl[mf][nt][0]);
                split_hilo2(p2, p3, pfh[mf][nt][1], pfl[mf][nt][1]);
            }
        }

#pragma unroll
        for (int kf = 0; kf < 2; kf++) {
#pragma unroll
            for (int p = 0; p < 4; p++) {
                unsigned bh4[4], bl4[4];
                ldsm_x4(bh4, vhb + p * (16 * 80) + kf * 32);
                ldsm_x4(bl4, vlb + p * (16 * 80) + kf * 32);
#pragma unroll
                for (int mf = 0; mf < 2; mf++) {
                    unsigned aph[4] = { pfh[mf][2 * kf][0], pfh[mf][2 * kf][1],
                                        pfh[mf][2 * kf + 1][0], pfh[mf][2 * kf + 1][1] };
                    unsigned apl[4] = { pfl[mf][2 * kf][0], pfl[mf][2 * kf][1],
                                        pfl[mf][2 * kf + 1][0], pfl[mf][2 * kf + 1][1] };
                    mma_bf16(o[mf][2 * p],     aph, bh4 + 0);
                    mma_bf16(o[mf][2 * p],     aph, bl4 + 0);
                    mma_bf16(o[mf][2 * p],     apl, bh4 + 0);
                    mma_bf16(o[mf][2 * p + 1], aph, bh4 + 2);
                    mma_bf16(o[mf][2 * p + 1], aph, bl4 + 2);
                    mma_bf16(o[mf][2 * p + 1], apl, bh4 + 2);
                }
            }
        }
        __syncthreads();
    }

#pragma unroll
    for (int mf = 0; mf < 2; mf++) {
        float l0 = lsum[mf][0], l1 = lsum[mf][1];
        l0 += __shfl_xor_sync(0xffffffffu, l0, 1);
        l0 += __shfl_xor_sync(0xffffffffu, l0, 2);
        l1 += __shfl_xor_sync(0xffffffffu, l1, 1);
        l1 += __shfl_xor_sync(0xffffffffu, l1, 2);
        const float rl0 = (l0 > 0.f) ? (1.f / l0) : 0.f;
        const float rl1 = (l1 > 0.f) ? (1.f / l1) : 0.f;

        const int qr0 = qbase + wq + mf * 16 + g;
        const size_t o0 = ((size_t)b * S_LEN + qr0) * DMODEL + h * HDIM;
        const size_t o1 = o0 + (size_t)8 * DMODEL;
#pragma unroll
        for (int dt = 0; dt < 8; dt++) {
            unsigned hiA, loA, hiB, loB;
            split_hilo2(o[mf][dt][0] * rl0, o[mf][dt][1] * rl0, hiA, loA);
            split_hilo2(o[mf][dt][2] * rl1, o[mf][dt][3] * rl1, hiB, loB);
            *(unsigned*)&ch[o0 + dt * 8 + t2] = hiA;
            *(unsigned*)&cl[o0 + dt * 8 + t2] = loA;
            *(unsigned*)&ch[o1 + dt * 8 + t2] = hiB;
            *(unsigned*)&cl[o1 + dt * 8 + t2] = loB;
        }
    }
}

// ---------------------------------------------------------------------------
extern "C" void kernel_launch(void* const* d_in, const int* in_sizes, int n_in,
                              void* d_out, int out_size)
{
    const float* hidden = (const float*)d_in[0];
    const void*  mask_raw = d_in[1];
    const float* q_w = (const float*)d_in[2];
    const float* q_b = (const float*)d_in[3];
    const float* k_w = (const float*)d_in[4];
    const float* k_b = (const float*)d_in[5];
    const float* v_w = (const float*)d_in[6];
    const float* v_b = (const float*)d_in[7];
    const float* out_w = (const float*)d_in[8];
    const float* out_b = (const float*)d_in[9];
    float* out = (float*)d_out;

    __nv_bfloat16 *ghh, *ghl, *gwh, *gwl, *gqh, *gql, *gkh, *gkl, *gvh, *gvl, *gch, *gcl;
    unsigned* gmb;
    cudaGetSymbolAddress((void**)&ghh, g_hh);
    cudaGetSymbolAddress((void**)&ghl, g_hl);
    cudaGetSymbolAddress((void**)&gwh, g_wh);
    cudaGetSymbolAddress((void**)&gwl, g_wl);
    cudaGetSymbolAddress((void**)&gqh, g_qh);
    cudaGetSymbolAddress((void**)&gql, g_ql);
    cudaGetSymbolAddress((void**)&gkh, g_kh);
    cudaGetSymbolAddress((void**)&gkl, g_kl);
    cudaGetSymbolAddress((void**)&gvh, g_vh);
    cudaGetSymbolAddress((void**)&gvl, g_vl);
    cudaGetSymbolAddress((void**)&gch, g_ch);
    cudaGetSymbolAddress((void**)&gcl, g_cl);
    cudaGetSymbolAddress((void**)&gmb, g_maskbits);

    static bool init_done = false;
    static cudaStream_t s2;
    static cudaEvent_t evFork, evJoin;
    if (!init_done) {
        cudaFuncSetAttribute(qkv_gemm_kernel,
            cudaFuncAttributeMaxDynamicSharedMemorySize, (int)GEMM_SMEM_BYTES);
        cudaFuncSetAttribute(out_gemm_kernel,
            cudaFuncAttributeMaxDynamicSharedMemorySize, (int)GEMM_SMEM_BYTES);
        cudaFuncSetAttribute(flash_mma_kernel,
            cudaFuncAttributeMaxDynamicSharedMemorySize, (int)FLASH_SMEM_BYTES);
        cudaStreamCreateWithFlags(&s2, cudaStreamNonBlocking);
        cudaEventCreateWithFlags(&evFork, cudaEventDisableTiming);
        cudaEventCreateWithFlags(&evJoin, cudaEventDisableTiming);
        init_done = true;
    }

    // (1) mask dtype detection (main stream)
    detect_mask_kernel<<<1, 256>>>((const unsigned char*)mask_raw);

    // fork: mask -> bitmask on side stream (overlaps cvt + QKV GEMM)
    cudaEventRecord(evFork, 0);
    cudaStreamWaitEvent(s2, evFork, 0);
    convert_maskbits_kernel<<<(MASK_N / 32 + 255) / 256, 256, 0, s2>>>(mask_raw, gmb);
    cudaEventRecord(evJoin, s2);

    // (2) fused hidden + weights hi/lo conversion (main stream)
    const int nh4 = NTOK * DMODEL / 4;
    dim3 cvtGrid((nh4 + 255) / 256, 5);
    cvt_all_kernel<<<cvtGrid, 256>>>(hidden, q_w, k_w, v_w, out_w, ghh, ghl, gwh, gwl);

    // (3) fused QKV projections
    dim3 qkvGrid(DMODEL / 128, NTOK / 128, 3);
    qkv_gemm_kernel<<<qkvGrid, 256, GEMM_SMEM_BYTES>>>(ghh, ghl, gwh, gwl,
        q_b, k_b, v_b, gqh, gql, gkh, gkl, gvh, gvl);

    // join: bitmask must be ready before flash
    cudaStreamWaitEvent(0, evJoin, 0);

    // (4) flash attention (128 q-rows per CTA)
    dim3 flashGrid(S_LEN / 128, NHEAD, BATCH);
    flash_mma_kernel<<<flashGrid, 128, FLASH_SMEM_BYTES>>>(gqh, gql, gkh, gkl, gvh, gvl,
        gmb, gch, gcl);

    // (5) output projection
    dim3 gemmGrid(DMODEL / 128, NTOK / 128);
    out_gemm_kernel<<<gemmGrid, 256, GEMM_SMEM_BYTES>>>(gch, gcl,
        gwh + 3 * (size_t)DMODEL * DMODEL, gwl + 3 * (size_t)DMODEL * DMODEL,
        out_b, out);
}

// round 16
// speedup vs baseline: 1.0140x; 1.0140x over previous
#include <cuda_runtime.h>
#include <cuda_bf16.h>
#include <cstdint>
#include <math.h>

// Problem constants
#define BATCH 4
#define S_LEN 2048
#define DMODEL 768
#define NHEAD 12
#define HDIM 64
#define NTOK (BATCH * S_LEN)            // 8192
#define MASK_N (NHEAD * S_LEN * S_LEN)  // 50331648

#define LOG2E 1.4426950408889634f

// -------------------- scratch (__device__ globals) -------------------------
__device__ __nv_bfloat16 g_hh[NTOK * DMODEL];
__device__ __nv_bfloat16 g_hl[NTOK * DMODEL];
__device__ __nv_bfloat16 g_wh[4][DMODEL * DMODEL];
__device__ __nv_bfloat16 g_wl[4][DMODEL * DMODEL];
__device__ __nv_bfloat16 g_qh[BATCH * NHEAD * S_LEN * HDIM];  // [b,h,s,d]
__device__ __nv_bfloat16 g_ql[BATCH * NHEAD * S_LEN * HDIM];
__device__ __nv_bfloat16 g_kh[BATCH * NHEAD * S_LEN * HDIM];
__device__ __nv_bfloat16 g_kl[BATCH * NHEAD * S_LEN * HDIM];
__device__ __nv_bfloat16 g_vh[BATCH * NHEAD * S_LEN * HDIM];  // [b,h,s,d] (like K)
__device__ __nv_bfloat16 g_vl[BATCH * NHEAD * S_LEN * HDIM];
__device__ __nv_bfloat16 g_ch[NTOK * DMODEL];
__device__ __nv_bfloat16 g_cl[NTOK * DMODEL];
__device__ unsigned g_maskbits[MASK_N / 32];
__device__ int g_mask_mode;

// ---------------------------------------------------------------------------
// cp.async / smem helpers
// ---------------------------------------------------------------------------
__device__ __forceinline__ unsigned smem_u32(const void* p)
{
    return (unsigned)__cvta_generic_to_shared(p);
}
__device__ __forceinline__ void cp16(void* s, const void* g)
{
    asm volatile("cp.async.cg.shared.global [%0], [%1], 16;"
                 :: "r"(smem_u32(s)), "l"(g));
}
__device__ __forceinline__ void cp4(void* s, const void* g)
{
    asm volatile("cp.async.ca.shared.global [%0], [%1], 4;"
                 :: "r"(smem_u32(s)), "l"(g));
}
#define CP_COMMIT() asm volatile("cp.async.commit_group;")
#define CP_WAIT0()  asm volatile("cp.async.wait_group 0;")
#define CP_WAIT1()  asm volatile("cp.async.wait_group 1;")

// ldmatrix x4 (non-transposed)
__device__ __forceinline__ void ldsm_x4(unsigned* r, unsigned addr)
{
    asm volatile("ldmatrix.sync.aligned.m8n8.x4.shared.b16 {%0,%1,%2,%3}, [%4];"
                 : "=r"(r[0]), "=r"(r[1]), "=r"(r[2]), "=r"(r[3]) : "r"(addr));
}
// ldmatrix x4 transposed (FA2 V-load pattern)
__device__ __forceinline__ void ldsm_x4_t(unsigned* r, unsigned addr)
{
    asm volatile("ldmatrix.sync.aligned.m8n8.x4.trans.shared.b16 {%0,%1,%2,%3}, [%4];"
                 : "=r"(r[0]), "=r"(r[1]), "=r"(r[2]), "=r"(r[3]) : "r"(addr));
}

// nonzero -> 1 bit (any-bit-set via sign trick)
__device__ __forceinline__ unsigned nz_bit(int x)
{
    return ((unsigned)(x | -x)) >> 31;
}

// ---------------------------------------------------------------------------
// Mask dtype detection (proven R4-R15)
// ---------------------------------------------------------------------------
__global__ void detect_mask_kernel(const unsigned char* __restrict__ m)
{
    __shared__ unsigned cnt[4];
    if (threadIdx.x < 4) cnt[threadIdx.x] = 0;
    __syncthreads();
    for (int i = threadIdx.x; i < 8192; i += blockDim.x)
        if (m[i]) atomicAdd(&cnt[i & 3], 1u);
    __syncthreads();
    if (threadIdx.x == 0) {
        int mode;
        if (cnt[1] + cnt[2] + cnt[3] == 0) mode = 1;   // int32 0/1
        else if (cnt[0] > 0)               mode = 0;   // uint8
        else                               mode = 2;   // float32
        g_mask_mode = mode;
    }
}

// Mask -> bitmask; each thread packs 32 consecutive elements.
__global__ void __launch_bounds__(256)
convert_maskbits_kernel(const void* __restrict__ mraw, unsigned* __restrict__ out)
{
    const int mode = g_mask_mode;
    const size_t t = (size_t)blockIdx.x * blockDim.x + threadIdx.x;
    if (t >= MASK_N / 32) return;
    unsigned w = 0;
    if (mode == 1) {
        const int4* p = (const int4*)mraw + t * 8;
#pragma unroll
        for (int i = 0; i < 8; i++) {
            int4 v = p[i];
            w |= nz_bit(v.x) << (i * 4);
            w |= nz_bit(v.y) << (i * 4 + 1);
            w |= nz_bit(v.z) << (i * 4 + 2);
            w |= nz_bit(v.w) << (i * 4 + 3);
        }
    } else if (mode == 0) {
        const uint4* p = (const uint4*)mraw + t * 2;
#pragma unroll
        for (int i = 0; i < 2; i++) {
            uint4 v = p[i];
            unsigned words[4] = { v.x, v.y, v.z, v.w };
#pragma unroll
            for (int j = 0; j < 4; j++)
#pragma unroll
                for (int bb = 0; bb < 4; bb++)
                    w |= (((words[j] >> (bb * 8)) & 0xFFu) ? 1u : 0u)
                         << (i * 16 + j * 4 + bb);
        }
    } else {
        const int4* p = (const int4*)mraw + t * 8;
#pragma unroll
        for (int i = 0; i < 8; i++) {
            int4 v = p[i];
            w |= nz_bit(v.x) << (i * 4);
            w |= nz_bit(v.y) << (i * 4 + 1);
            w |= nz_bit(v.z) << (i * 4 + 2);
            w |= nz_bit(v.w) << (i * 4 + 3);
        }
    }
    out[t] = w;
}

// ---------------------------------------------------------------------------
// fp32 -> bf16 hi/lo split
// ---------------------------------------------------------------------------
__device__ __forceinline__ unsigned pack_bf16x2(float x, float y)
{
    __nv_bfloat162 t = __float22bfloat162_rn(make_float2(x, y));
    return *(unsigned*)&t;
}

__device__ __forceinline__ void split_hilo2(float x, float y, unsigned& hi, unsigned& lo)
{
    hi = pack_bf16x2(x, y);
    float hx = __uint_as_float(hi << 16);
    float hy = __uint_as_float(hi & 0xffff0000u);
    lo = pack_bf16x2(x - hx, y - hy);
}

// Fused: convert hidden (y==4) + all 4 weights (y==0..3)
__global__ void __launch_bounds__(256)
cvt_all_kernel(const float* __restrict__ hid,
               const float* __restrict__ w0, const float* __restrict__ w1,
               const float* __restrict__ w2, const float* __restrict__ w3,
               __nv_bfloat16* __restrict__ HH, __nv_bfloat16* __restrict__ HL,
               __nv_bfloat16* __restrict__ WH, __nv_bfloat16* __restrict__ WL)
{
    const int y = blockIdx.y;
    const int i = blockIdx.x * blockDim.x + threadIdx.x;
    const float* x;
    __nv_bfloat16 *h, *l;
    int n4;
    if (y == 4) {
        n4 = NTOK * DMODEL / 4;
        x = hid; h = HH; l = HL;
    } else {
        n4 = DMODEL * DMODEL / 4;
        x = (y == 0) ? w0 : (y == 1) ? w1 : (y == 2) ? w2 : w3;
        h = WH + (size_t)y * DMODEL * DMODEL;
        l = WL + (size_t)y * DMODEL * DMODEL;
    }
    if (i >= n4) return;
    float4 v = ((const float4*)x)[i];
    uint2 ph, pl;
    split_hilo2(v.x, v.y, ph.x, pl.x);
    split_hilo2(v.z, v.w, ph.y, pl.y);
    ((uint2*)h)[i] = ph;
    ((uint2*)l)[i] = pl;
}

// ---------------------------------------------------------------------------
// mma.sync m16n8k16 bf16 (f32 accumulate)
// ---------------------------------------------------------------------------
__device__ __forceinline__ void mma_bf16(float* c, const unsigned* a, const unsigned* b)
{
    asm volatile(
        "mma.sync.aligned.m16n8k16.row.col.f32.bf16.bf16.f32 "
        "{%0,%1,%2,%3},{%4,%5,%6,%7},{%8,%9},{%0,%1,%2,%3};"
        : "+f"(c[0]), "+f"(c[1]), "+f"(c[2]), "+f"(c[3])
        : "r"(a[0]), "r"(a[1]), "r"(a[2]), "r"(a[3]),
          "r"(b[0]), "r"(b[1]));
}

// ---------------------------------------------------------------------------
// GEMM core (R12-proven)
// ---------------------------------------------------------------------------
struct GemmSmem {
    __nv_bfloat16 Ahs[128][40];
    __nv_bfloat16 Als[128][40];
    __nv_bfloat16 Whs[128][40];
    __nv_bfloat16 Wls[128][40];
};
#define GEMM_SMEM_BYTES (2 * sizeof(GemmSmem))

__device__ __forceinline__ void gemm_load_stage(
    GemmSmem& sm, const __nv_bfloat16* __restrict__ Ah, const __nv_bfloat16* __restrict__ Al,
    const __nv_bfloat16* __restrict__ Wh, const __nv_bfloat16* __restrict__ Wl,
    int bm, int bn, int k0, int tid)
{
#pragma unroll
    for (int it = 0; it < 2; it++) {
        int fid = tid + it * 256;
        int row = fid >> 2, cc = (fid & 3) * 8;
        cp16(&sm.Ahs[row][cc], &Ah[(size_t)(bm + row) * DMODEL + k0 + cc]);
        cp16(&sm.Als[row][cc], &Al[(size_t)(bm + row) * DMODEL + k0 + cc]);
        cp16(&sm.Whs[row][cc], &Wh[(size_t)(bn + row) * DMODEL + k0 + cc]);
        cp16(&sm.Wls[row][cc], &Wl[(size_t)(bn + row) * DMODEL + k0 + cc]);
    }
}

__device__ __forceinline__ void gemm_tile(
    GemmSmem* bufs, const __nv_bfloat16* __restrict__ Ah, const __nv_bfloat16* __restrict__ Al,
    const __nv_bfloat16* __restrict__ Wh, const __nv_bfloat16* __restrict__ Wl,
    int bm, int bn, float c[16][4])
{
    const int tid  = threadIdx.x;
    const int lane = tid & 31;
    const int w    = tid >> 5;
    const int wm   = w >> 2;
    const int wn   = w & 3;
    const int NKT  = DMODEL / 32;   // 24

    const unsigned lbA = (unsigned)(((lane & 7) + ((lane >> 3) & 1) * 8) * 80
                                    + ((lane >> 4) & 1) * 16);
    const unsigned lbB = (unsigned)(((lane & 7) + ((lane >> 4) & 1) * 8) * 80
                                    + ((lane >> 3) & 1) * 16);

#pragma unroll
    for (int i = 0; i < 16; i++)
#pragma unroll
        for (int j = 0; j < 4; j++) c[i][j] = 0.f;

    gemm_load_stage(bufs[0], Ah, Al, Wh, Wl, bm, bn, 0, tid);
    CP_COMMIT();

    for (int kt = 0; kt < NKT; kt++) {
        if (kt + 1 < NKT) {
            gemm_load_stage(bufs[(kt + 1) & 1], Ah, Al, Wh, Wl, bm, bn, (kt + 1) * 32, tid);
            CP_COMMIT();
            CP_WAIT1();
        } else {
            CP_WAIT0();
        }
        __syncthreads();
        GemmSmem& sm = bufs[kt & 1];
        const unsigned ahb = smem_u32(&sm.Ahs[0][0]) + (wm * 64) * 80 + lbA;
        const unsigned alb = smem_u32(&sm.Als[0][0]) + (wm * 64) * 80 + lbA;
        const unsigned whb = smem_u32(&sm.Whs[0][0]) + (wn * 32) * 80 + lbB;
        const unsigned wlb = smem_u32(&sm.Wls[0][0]) + (wn * 32) * 80 + lbB;

#pragma unroll
        for (int kf = 0; kf < 2; kf++) {
            unsigned ah[4][4], al[4][4];
#pragma unroll
            for (int mf = 0; mf < 4; mf++) {
                ldsm_x4(ah[mf], ahb + mf * (16 * 80) + kf * 32);
                ldsm_x4(al[mf], alb + mf * (16 * 80) + kf * 32);
            }
            unsigned wh_[2][4], wl_[2][4];
#pragma unroll
            for (int p = 0; p < 2; p++) {
                ldsm_x4(wh_[p], whb + p * (16 * 80) + kf * 32);
                ldsm_x4(wl_[p], wlb + p * (16 * 80) + kf * 32);
            }
#pragma unroll
            for (int mf = 0; mf < 4; mf++)
#pragma unroll
                for (int nf = 0; nf < 4; nf++) {
                    const unsigned* bh = &wh_[nf >> 1][(nf & 1) * 2];
                    const unsigned* bl = &wl_[nf >> 1][(nf & 1) * 2];
                    mma_bf16(c[mf * 4 + nf], ah[mf], bh);
                    mma_bf16(c[mf * 4 + nf], ah[mf], bl);
                    mma_bf16(c[mf * 4 + nf], al[mf], bh);
                }
        }
        __syncthreads();
    }
}

// ---------------------------------------------------------------------------
// Fused QKV projection: grid.z = 0(Q),1(K),2(V). Q pre-scaled by 0.125*log2(e).
// UNIFORM epilogue: all three in [b,h,s,d] hi/lo (V no longer transposed).
// ---------------------------------------------------------------------------
__global__ void __launch_bounds__(256)
qkv_gemm_kernel(const __nv_bfloat16* __restrict__ Ah, const __nv_bfloat16* __restrict__ Al,
                const __nv_bfloat16* __restrict__ WhB, const __nv_bfloat16* __restrict__ WlB,
                const float* __restrict__ bq, const float* __restrict__ bk,
                const float* __restrict__ bv,
                __nv_bfloat16* __restrict__ QH, __nv_bfloat16* __restrict__ QL,
                __nv_bfloat16* __restrict__ KH, __nv_bfloat16* __restrict__ KL,
                __nv_bfloat16* __restrict__ VH, __nv_bfloat16* __restrict__ VL)
{
    extern __shared__ char smem_raw[];
    GemmSmem* bufs = (GemmSmem*)smem_raw;

    const int z = blockIdx.z;
    const __nv_bfloat16* Wh = WhB + (size_t)z * DMODEL * DMODEL;
    const __nv_bfloat16* Wl = WlB + (size_t)z * DMODEL * DMODEL;
    const float* bias = (z == 0) ? bq : (z == 1) ? bk : bv;
    const float scale = (z == 0) ? (0.125f * LOG2E) : 1.0f;
    __nv_bfloat16* CH = (z == 0) ? QH : (z == 1) ? KH : VH;
    __nv_bfloat16* CL = (z == 0) ? QL : (z == 1) ? KL : VL;

    const int bm = blockIdx.y * 128;
    const int bn = blockIdx.x * 128;
    float c[16][4];
    gemm_tile(bufs, Ah, Al, Wh, Wl, bm, bn, c);

    const int tid  = threadIdx.x;
    const int lane = tid & 31;
    const int w    = tid >> 5;
    const int g    = lane >> 2;
    const int t2   = (lane & 3) * 2;
    const int wm   = w >> 2;
    const int wn   = w & 3;

#pragma unroll
    for (int mf = 0; mf < 4; mf++) {
#pragma unroll
        for (int nf = 0; nf < 4; nf++) {
            const int colb = bn + wn * 32 + nf * 8 + t2;
            const float b0 = bias[colb], b1 = bias[colb + 1];
            float v[4] = { (c[mf * 4 + nf][0] + b0) * scale, (c[mf * 4 + nf][1] + b1) * scale,
                           (c[mf * 4 + nf][2] + b0) * scale, (c[mf * 4 + nf][3] + b1) * scale };
#pragma unroll
            for (int half = 0; half < 2; half++) {
                const int m = bm + wm * 64 + mf * 16 + g + half * 8;
                const float x0 = v[half * 2], x1 = v[half * 2 + 1];
                const int b = m >> 11;
                const int s = m & 2047;
                const int h = colb >> 6;
                const int d = colb & 63;
                unsigned hi, lo;
                split_hilo2(x0, x1, hi, lo);
                size_t idx = (((size_t)b * NHEAD + h) * S_LEN + s) * HDIM + d;
                *(unsigned*)&CH[idx] = hi;
                *(unsigned*)&CL[idx] = lo;
            }
        }
    }
}

// ---------------------------------------------------------------------------
// Output projection: plain fp32 [m,n]
// ---------------------------------------------------------------------------
__global__ void __launch_bounds__(256)
out_gemm_kernel(const __nv_bfloat16* __restrict__ Ah, const __nv_bfloat16* __restrict__ Al,
                const __nv_bfloat16* __restrict__ Wh, const __nv_bfloat16* __restrict__ Wl,
                const float* __restrict__ bias, float* __restrict__ Cf)
{
    extern __shared__ char smem_raw[];
    GemmSmem* bufs = (GemmSmem*)smem_raw;

    const int bm = blockIdx.y * 128;
    const int bn = blockIdx.x * 128;
    float c[16][4];
    gemm_tile(bufs, Ah, Al, Wh, Wl, bm, bn, c);

    const int tid  = threadIdx.x;
    const int lane = tid & 31;
    const int w    = tid >> 5;
    const int g    = lane >> 2;
    const int t2   = (lane & 3) * 2;
    const int wm   = w >> 2;
    const int wn   = w & 3;

#pragma unroll
    for (int mf = 0; mf < 4; mf++)
#pragma unroll
        for (int nf = 0; nf < 4; nf++) {
            const int colb = bn + wn * 32 + nf * 8 + t2;
            const float b0 = bias[colb], b1 = bias[colb + 1];
#pragma unroll
            for (int half = 0; half < 2; half++) {
                const int m = bm + wm * 64 + mf * 16 + g + half * 8;
                float2 p = { c[mf * 4 + nf][half * 2] + b0,
                             c[mf * 4 + nf][half * 2 + 1] + b1 };
                *(float2*)&Cf[(size_t)m * DMODEL + colb] = p;
            }
        }
}

#define MASKVAL (-1e30f)

// ---------------------------------------------------------------------------
// Flash attention: 32 q-rows per warp, 32-key tiles, exp2, V via ldmatrix.trans.
// K and V both stored/loaded as [key][d] rows (stride 144B). grid (S/128,H,B).
// ---------------------------------------------------------------------------
#define KT_KEYS 32
struct FlashSmem {
    __nv_bfloat16 kh[KT_KEYS][72];   // [key][d] stride 144B
    __nv_bfloat16 kl[KT_KEYS][72];
    __nv_bfloat16 vh[KT_KEYS][72];   // [key][d] stride 144B (trans-loaded for PV)
    __nv_bfloat16 vl[KT_KEYS][72];
    unsigned m32[128];
};
#define FLASH_SMEM_BYTES (2 * sizeof(FlashSmem))

__global__ void __launch_bounds__(128)
flash_mma_kernel(const __nv_bfloat16* __restrict__ qh, const __nv_bfloat16* __restrict__ ql,
                 const __nv_bfloat16* __restrict__ kh, const __nv_bfloat16* __restrict__ kl,
                 const __nv_bfloat16* __restrict__ vh, const __nv_bfloat16* __restrict__ vl,
                 const unsigned* __restrict__ mbits,
                 __nv_bfloat16* __restrict__ ch, __nv_bfloat16* __restrict__ cl)
{
    extern __shared__ char smem_raw[];
    FlashSmem* bufs = (FlashSmem*)smem_raw;

    const int tid  = threadIdx.x;
    const int w    = tid >> 5;
    const int lane = tid & 31;
    const int g    = lane >> 2;
    const int t2   = (lane & 3) * 2;
    const int qt = blockIdx.x, h = blockIdx.y, b = blockIdx.z;
    const int qbase = qt * 128;
    const int wq = w * 32;

    const size_t bh   = (size_t)(b * NHEAD + h);
    const size_t kvb  = bh * S_LEN * HDIM;
    const size_t mb32 = ((size_t)h * S_LEN + qbase) * (S_LEN / 32);
    const int NT = S_LEN / KT_KEYS;   // 64

    // K (non-trans B-frag): rows = keys, n=(l&7)+((l>>4)&1)*8, k-half=(l>>3)&1
    const unsigned lbK = (unsigned)(((lane & 7) + ((lane >> 4) & 1) * 8) * 144
                                    + ((lane >> 3) & 1) * 16);
    // V (trans B-frag): tile rows = keys (l&7) + 8*((l>>3)&1), d-half (l>>4)*8
    const unsigned lbVt = (unsigned)(((lane & 7) + ((lane >> 3) & 1) * 8) * 144
                                     + (lane >> 4) * 16);

    auto load_stage = [&](int buf, int kt) {
        FlashSmem& sm = bufs[buf];
#pragma unroll
        for (int it = 0; it < 2; it++) {
            int fid = tid + it * 128;
            int krow = fid >> 3, kcc = (fid & 7) * 8;
            cp16(&sm.kh[krow][kcc], &kh[kvb + (size_t)(kt * KT_KEYS + krow) * HDIM + kcc]);
            cp16(&sm.kl[krow][kcc], &kl[kvb + (size_t)(kt * KT_KEYS + krow) * HDIM + kcc]);
            cp16(&sm.vh[krow][kcc], &vh[kvb + (size_t)(kt * KT_KEYS + krow) * HDIM + kcc]);
            cp16(&sm.vl[krow][kcc], &vl[kvb + (size_t)(kt * KT_KEYS + krow) * HDIM + kcc]);
        }
        cp4(&sm.m32[tid], &mbits[mb32 + (size_t)tid * (S_LEN / 32) + kt]);
    };

    unsigned qfh[2][4][4], qfl[2][4][4];
#pragma unroll
    for (int mf = 0; mf < 2; mf++) {
        const size_t r0 = (size_t)(qbase + wq + mf * 16 + g) * HDIM;
        const size_t r1 = r0 + 8 * HDIM;
        const __nv_bfloat16* ph = qh + kvb;
        const __nv_bfloat16* pl = ql + kvb;
#pragma unroll
        for (int kf = 0; kf < 4; kf++) {
            int c0 = kf * 16 + t2, c1 = c0 + 8;
            qfh[mf][kf][0] = *(const unsigned*)&ph[r0 + c0];
            qfh[mf][kf][1] = *(const unsigned*)&ph[r1 + c0];
            qfh[mf][kf][2] = *(const unsigned*)&ph[r0 + c1];
            qfh[mf][kf][3] = *(const unsigned*)&ph[r1 + c1];
            qfl[mf][kf][0] = *(const unsigned*)&pl[r0 + c0];
            qfl[mf][kf][1] = *(const unsigned*)&pl[r1 + c0];
            qfl[mf][kf][2] = *(const unsigned*)&pl[r0 + c1];
            qfl[mf][kf][3] = *(const unsigned*)&pl[r1 + c1];
        }
    }

    float o[2][8][4];
#pragma unroll
    for (int mf = 0; mf < 2; mf++)
#pragma unroll
        for (int dt = 0; dt < 8; dt++)
#pragma unroll
            for (int i = 0; i < 4; i++) o[mf][dt][i] = 0.f;
    float lsum[2][2] = { {0.f, 0.f}, {0.f, 0.f} };

    load_stage(0, 0);
    CP_COMMIT();

    for (int kt = 0; kt < NT; kt++) {
        if (kt + 1 < NT) {
            load_stage((kt + 1) & 1, kt + 1);
            CP_COMMIT();
            CP_WAIT1();
        } else {
            CP_WAIT0();
        }
        __syncthreads();
        FlashSmem& sm = bufs[kt & 1];
        const unsigned khb = smem_u32(&sm.kh[0][0]) + lbK;
        const unsigned klb = smem_u32(&sm.kl[0][0]) + lbK;
        const unsigned vhb = smem_u32(&sm.vh[0][0]) + lbVt;
        const unsigned vlb = smem_u32(&sm.vl[0][0]) + lbVt;

        // ---- S = Q K^T ----
        float sacc[2][4][4];
#pragma unroll
        for (int mf = 0; mf < 2; mf++)
#pragma unroll
            for (int nt = 0; nt < 4; nt++)
#pragma unroll
                for (int i = 0; i < 4; i++) sacc[mf][nt][i] = 0.f;

#pragma unroll
        for (int kf = 0; kf < 4; kf++) {
#pragma unroll
            for (int p = 0; p < 2; p++) {
                unsigned bh4[4], bl4[4];
                ldsm_x4(bh4, khb + p * (16 * 144) + kf * 32);
                ldsm_x4(bl4, klb + p * (16 * 144) + kf * 32);
#pragma unroll
                for (int mf = 0; mf < 2; mf++) {
                    mma_bf16(sacc[mf][2 * p],     qfh[mf][kf], bh4 + 0);
                    mma_bf16(sacc[mf][2 * p],     qfh[mf][kf], bl4 + 0);
                    mma_bf16(sacc[mf][2 * p],     qfl[mf][kf], bh4 + 0);
                    mma_bf16(sacc[mf][2 * p + 1], qfh[mf][kf], bh4 + 2);
                    mma_bf16(sacc[mf][2 * p + 1], qfh[mf][kf], bl4 + 2);
                    mma_bf16(sacc[mf][2 * p + 1], qfl[mf][kf], bh4 + 2);
                }
            }
        }

        // ---- mask + p = exp2(s) + hi/lo split ----
        unsigned pfh[2][4][2], pfl[2][4][2];
#pragma unroll
        for (int mf = 0; mf < 2; mf++) {
            const unsigned w0 = sm.m32[wq + mf * 16 + g] >> t2;
            const unsigned w1 = sm.m32[wq + mf * 16 + 8 + g] >> t2;
#pragma unroll
            for (int nt = 0; nt < 4; nt++) {
                unsigned b0 = w0 >> (nt * 8);
                unsigned b1 = w1 >> (nt * 8);
                float s0 = (b0 & 1u) ? sacc[mf][nt][0] : MASKVAL;
                float s1 = (b0 & 2u) ? sacc[mf][nt][1] : MASKVAL;
                float s2 = (b1 & 1u) ? sacc[mf][nt][2] : MASKVAL;
                float s3 = (b1 & 2u) ? sacc[mf][nt][3] : MASKVAL;
                float p0 = exp2f(s0);
                float p1 = exp2f(s1);
                float p2 = exp2f(s2);
                float p3 = exp2f(s3);
                lsum[mf][0] += p0 + p1;
                lsum[mf][1] += p2 + p3;
                split_hilo2(p0, p1, pfh[mf][nt][0], pfl[mf][nt][0]);
                split_hilo2(p2, p3, pfh[mf][nt][1], pfl[mf][nt][1]);
            }
        }

        // ---- O += P V : V B-frags via ldmatrix.trans on [key][d] tiles ----
        // kc = 16-key chunk; dg = 16-d group. x4.trans tiles: r0/r1 = d-half 0
        // (k 0-7 / 8-15), r2/r3 = d-half 1.
#pragma unroll
        for (int kc = 0; kc < 2; kc++) {
#pragma unroll
            for (int dg = 0; dg < 4; dg++) {
                unsigned bh4[4], bl4[4];
                ldsm_x4_t(bh4, vhb + kc * (16 * 144) + dg * 32);
                ldsm_x4_t(bl4, vlb + kc * (16 * 144) + dg * 32);
#pragma unroll
                for (int mf = 0; mf < 2; mf++) {
                    unsigned aph[4] = { pfh[mf][2 * kc][0], pfh[mf][2 * kc][1],
                                        pfh[mf][2 * kc + 1][0], pfh[mf][2 * kc + 1][1] };
                    unsigned apl[4] = { pfl[mf][2 * kc][0], pfl[mf][2 * kc][1],
                                        pfl[mf][2 * kc + 1][0], pfl[mf][2 * kc + 1][1] };
                    mma_bf16(o[mf][2 * dg],     aph, bh4 + 0);
                    mma_bf16(o[mf][2 * dg],     aph, bl4 + 0);
                    mma_bf16(o[mf][2 * dg],     apl, bh4 + 0);
                    mma_bf16(o[mf][2 * dg + 1], aph, bh4 + 2);
                    mma_bf16(o[mf][2 * dg + 1], aph, bl4 + 2);
                    mma_bf16(o[mf][2 * dg + 1], apl, bh4 + 2);
                }
            }
        }
        __syncthreads();
    }

#pragma unroll
    for (int mf = 0; mf < 2; mf++) {
        float l0 = lsum[mf][0], l1 = lsum[mf][1];
        l0 += __shfl_xor_sync(0xffffffffu, l0, 1);
        l0 += __shfl_xor_sync(0xffffffffu, l0, 2);
        l1 += __shfl_xor_sync(0xffffffffu, l1, 1);
        l1 += __shfl_xor_sync(0xffffffffu, l1, 2);
        const float rl0 = (l0 > 0.f) ? (1.f / l0) : 0.f;
        const float rl1 = (l1 > 0.f) ? (1.f / l1) : 0.f;

        const int qr0 = qbase + wq + mf * 16 + g;
        const size_t o0 = ((size_t)b * S_LEN + qr0) * DMODEL + h * HDIM;
        const size_t o1 = o0 + (size_t)8 * DMODEL;
#pragma unroll
        for (int dt = 0; dt < 8; dt++) {
            unsigned hiA, loA, hiB, loB;
            split_hilo2(o[mf][dt][0] * rl0, o[mf][dt][1] * rl0, hiA, loA);
            split_hilo2(o[mf][dt][2] * rl1, o[mf][dt][3] * rl1, hiB, loB);
            *(unsigned*)&ch[o0 + dt * 8 + t2] = hiA;
            *(unsigned*)&cl[o0 + dt * 8 + t2] = loA;
            *(unsigned*)&ch[o1 + dt * 8 + t2] = hiB;
            *(unsigned*)&cl[o1 + dt * 8 + t2] = loB;
        }
    }
}

// ---------------------------------------------------------------------------
extern "C" void kernel_launch(void* const* d_in, const int* in_sizes, int n_in,
                              void* d_out, int out_size)
{
    const float* hidden = (const float*)d_in[0];
    const void*  mask_raw = d_in[1];
    const float* q_w = (const float*)d_in[2];
    const float* q_b = (const float*)d_in[3];
    const float* k_w = (const float*)d_in[4];
    const float* k_b = (const float*)d_in[5];
    const float* v_w = (const float*)d_in[6];
    const float* v_b = (const float*)d_in[7];
    const float* out_w = (const float*)d_in[8];
    const float* out_b = (const float*)d_in[9];
    float* out = (float*)d_out;

    __nv_bfloat16 *ghh, *ghl, *gwh, *gwl, *gqh, *gql, *gkh, *gkl, *gvh, *gvl, *gch, *gcl;
    unsigned* gmb;
    cudaGetSymbolAddress((void**)&ghh, g_hh);
    cudaGetSymbolAddress((void**)&ghl, g_hl);
    cudaGetSymbolAddress((void**)&gwh, g_wh);
    cudaGetSymbolAddress((void**)&gwl, g_wl);
    cudaGetSymbolAddress((void**)&gqh, g_qh);
    cudaGetSymbolAddress((void**)&gql, g_ql);
    cudaGetSymbolAddress((void**)&gkh, g_kh);
    cudaGetSymbolAddress((void**)&gkl, g_kl);
    cudaGetSymbolAddress((void**)&gvh, g_vh);
    cudaGetSymbolAddress((void**)&gvl, g_vl);
    cudaGetSymbolAddress((void**)&gch, g_ch);
    cudaGetSymbolAddress((void**)&gcl, g_cl);
    cudaGetSymbolAddress((void**)&gmb, g_maskbits);

    static bool init_done = false;
    static cudaStream_t s2;
    static cudaEvent_t evFork, evJoin;
    if (!init_done) {
        cudaFuncSetAttribute(qkv_gemm_kernel,
            cudaFuncAttributeMaxDynamicSharedMemorySize, (int)GEMM_SMEM_BYTES);
        cudaFuncSetAttribute(out_gemm_kernel,
            cudaFuncAttributeMaxDynamicSharedMemorySize, (int)GEMM_SMEM_BYTES);
        cudaFuncSetAttribute(flash_mma_kernel,
            cudaFuncAttributeMaxDynamicSharedMemorySize, (int)FLASH_SMEM_BYTES);
        cudaStreamCreateWithFlags(&s2, cudaStreamNonBlocking);
        cudaEventCreateWithFlags(&evFork, cudaEventDisableTiming);
        cudaEventCreateWithFlags(&evJoin, cudaEventDisableTiming);
        init_done = true;
    }

    // (1) mask dtype detection (main stream)
    detect_mask_kernel<<<1, 256>>>((const unsigned char*)mask_raw);

    // fork: mask -> bitmask on side stream (overlaps cvt + QKV GEMM)
    cudaEventRecord(evFork, 0);
    cudaStreamWaitEvent(s2, evFork, 0);
    convert_maskbits_kernel<<<(MASK_N / 32 + 255) / 256, 256, 0, s2>>>(mask_raw, gmb);
    cudaEventRecord(evJoin, s2);

    // (2) fused hidden + weights hi/lo conversion (main stream)
    const int nh4 = NTOK * DMODEL / 4;
    dim3 cvtGrid((nh4 + 255) / 256, 5);
    cvt_all_kernel<<<cvtGrid, 256>>>(hidden, q_w, k_w, v_w, out_w, ghh, ghl, gwh, gwl);

    // (3) fused QKV projections (uniform epilogue)
    dim3 qkvGrid(DMODEL / 128, NTOK / 128, 3);
    qkv_gemm_kernel<<<qkvGrid, 256, GEMM_SMEM_BYTES>>>(ghh, ghl, gwh, gwl,
        q_b, k_b, v_b, gqh, gql, gkh, gkl, gvh, gvl);

    // join: bitmask must be ready before flash
    cudaStreamWaitEvent(0, evJoin, 0);

    // (4) flash attention (128 q-rows per CTA, V via ldmatrix.trans)
    dim3 flashGrid(S_LEN / 128, NHEAD, BATCH);
    flash_mma_kernel<<<flashGrid, 128, FLASH_SMEM_BYTES>>>(gqh, gql, gkh, gkl, gvh, gvl,
        gmb, gch, gcl);

    // (5) output projection
    dim3 gemmGrid(DMODEL / 128, NTOK / 128);
    out_gemm_kernel<<<gemmGrid, 256, GEMM_SMEM_BYTES>>>(gch, gcl,
        gwh + 3 * (size_t)DMODEL * DMODEL, gwl + 3 * (size_t)DMODEL * DMODEL,
        out_b, out);
}

// round 17
// speedup vs baseline: 1.0501x; 1.0356x over previous
#include <cuda_runtime.h>
#include <cuda_bf16.h>
#include <cstdint>
#include <math.h>

// Problem constants
#define BATCH 4
#define S_LEN 2048
#define DMODEL 768
#define NHEAD 12
#define HDIM 64
#define NTOK (BATCH * S_LEN)            // 8192
#define MASK_N (NHEAD * S_LEN * S_LEN)  // 50331648

#define LOG2E 1.4426950408889634f

// -------------------- scratch (__device__ globals) -------------------------
__device__ __nv_bfloat16 g_hh[NTOK * DMODEL];
__device__ __nv_bfloat16 g_hl[NTOK * DMODEL];
__device__ __nv_bfloat16 g_wh[4][DMODEL * DMODEL];
__device__ __nv_bfloat16 g_wl[4][DMODEL * DMODEL];
__device__ __nv_bfloat16 g_qh[BATCH * NHEAD * S_LEN * HDIM];  // [b,h,s,d]
__device__ __nv_bfloat16 g_ql[BATCH * NHEAD * S_LEN * HDIM];
__device__ __nv_bfloat16 g_kh[BATCH * NHEAD * S_LEN * HDIM];
__device__ __nv_bfloat16 g_kl[BATCH * NHEAD * S_LEN * HDIM];
__device__ __nv_bfloat16 g_vh[BATCH * NHEAD * S_LEN * HDIM];  // [b,h,s,d]
__device__ __nv_bfloat16 g_vl[BATCH * NHEAD * S_LEN * HDIM];
__device__ __nv_bfloat16 g_ch[NTOK * DMODEL];
__device__ __nv_bfloat16 g_cl[NTOK * DMODEL];
__device__ unsigned g_maskbits[MASK_N / 32];
__device__ int g_mask_mode;

// ---------------------------------------------------------------------------
// cp.async / smem helpers
// ---------------------------------------------------------------------------
__device__ __forceinline__ unsigned smem_u32(const void* p)
{
    return (unsigned)__cvta_generic_to_shared(p);
}
__device__ __forceinline__ void cp16(void* s, const void* g)
{
    asm volatile("cp.async.cg.shared.global [%0], [%1], 16;"
                 :: "r"(smem_u32(s)), "l"(g));
}
__device__ __forceinline__ void cp4(void* s, const void* g)
{
    asm volatile("cp.async.ca.shared.global [%0], [%1], 4;"
                 :: "r"(smem_u32(s)), "l"(g));
}
#define CP_COMMIT() asm volatile("cp.async.commit_group;")
#define CP_WAIT0()  asm volatile("cp.async.wait_group 0;")
#define CP_WAIT1()  asm volatile("cp.async.wait_group 1;")

// ldmatrix x4 (non-transposed)
__device__ __forceinline__ void ldsm_x4(unsigned* r, unsigned addr)
{
    asm volatile("ldmatrix.sync.aligned.m8n8.x4.shared.b16 {%0,%1,%2,%3}, [%4];"
                 : "=r"(r[0]), "=r"(r[1]), "=r"(r[2]), "=r"(r[3]) : "r"(addr));
}
// ldmatrix x4 transposed (FA2 V-load pattern)
__device__ __forceinline__ void ldsm_x4_t(unsigned* r, unsigned addr)
{
    asm volatile("ldmatrix.sync.aligned.m8n8.x4.trans.shared.b16 {%0,%1,%2,%3}, [%4];"
                 : "=r"(r[0]), "=r"(r[1]), "=r"(r[2]), "=r"(r[3]) : "r"(addr));
}

// nonzero -> 1 bit
__device__ __forceinline__ unsigned nz_bit(int x)
{
    return ((unsigned)(x | -x)) >> 31;
}

// ---------------------------------------------------------------------------
// Mask dtype detection (proven R4-R16)
// ---------------------------------------------------------------------------
__global__ void detect_mask_kernel(const unsigned char* __restrict__ m)
{
    __shared__ unsigned cnt[4];
    if (threadIdx.x < 4) cnt[threadIdx.x] = 0;
    __syncthreads();
    for (int i = threadIdx.x; i < 8192; i += blockDim.x)
        if (m[i]) atomicAdd(&cnt[i & 3], 1u);
    __syncthreads();
    if (threadIdx.x == 0) {
        int mode;
        if (cnt[1] + cnt[2] + cnt[3] == 0) mode = 1;   // int32 0/1
        else if (cnt[0] > 0)               mode = 0;   // uint8
        else                               mode = 2;   // float32
        g_mask_mode = mode;
    }
}

// Mask -> bitmask; each thread packs 32 consecutive elements.
__global__ void __launch_bounds__(256)
convert_maskbits_kernel(const void* __restrict__ mraw, unsigned* __restrict__ out)
{
    const int mode = g_mask_mode;
    const size_t t = (size_t)blockIdx.x * blockDim.x + threadIdx.x;
    if (t >= MASK_N / 32) return;
    unsigned w = 0;
    if (mode == 1) {
        const int4* p = (const int4*)mraw + t * 8;
#pragma unroll
        for (int i = 0; i < 8; i++) {
            int4 v = p[i];
            w |= nz_bit(v.x) << (i * 4);
            w |= nz_bit(v.y) << (i * 4 + 1);
            w |= nz_bit(v.z) << (i * 4 + 2);
            w |= nz_bit(v.w) << (i * 4 + 3);
        }
    } else if (mode == 0) {
        const uint4* p = (const uint4*)mraw + t * 2;
#pragma unroll
        for (int i = 0; i < 2; i++) {
            uint4 v = p[i];
            unsigned words[4] = { v.x, v.y, v.z, v.w };
#pragma unroll
            for (int j = 0; j < 4; j++)
#pragma unroll
                for (int bb = 0; bb < 4; bb++)
                    w |= (((words[j] >> (bb * 8)) & 0xFFu) ? 1u : 0u)
                         << (i * 16 + j * 4 + bb);
        }
    } else {
        const int4* p = (const int4*)mraw + t * 8;
#pragma unroll
        for (int i = 0; i < 8; i++) {
            int4 v = p[i];
            w |= nz_bit(v.x) << (i * 4);
            w |= nz_bit(v.y) << (i * 4 + 1);
            w |= nz_bit(v.z) << (i * 4 + 2);
            w |= nz_bit(v.w) << (i * 4 + 3);
        }
    }
    out[t] = w;
}

// ---------------------------------------------------------------------------
// fp32 -> bf16 hi/lo split
// ---------------------------------------------------------------------------
__device__ __forceinline__ unsigned pack_bf16x2(float x, float y)
{
    __nv_bfloat162 t = __float22bfloat162_rn(make_float2(x, y));
    return *(unsigned*)&t;
}

__device__ __forceinline__ void split_hilo2(float x, float y, unsigned& hi, unsigned& lo)
{
    hi = pack_bf16x2(x, y);
    float hx = __uint_as_float(hi << 16);
    float hy = __uint_as_float(hi & 0xffff0000u);
    lo = pack_bf16x2(x - hx, y - hy);
}

// Fused: convert hidden (y==4) + all 4 weights (y==0..3)
__global__ void __launch_bounds__(256)
cvt_all_kernel(const float* __restrict__ hid,
               const float* __restrict__ w0, const float* __restrict__ w1,
               const float* __restrict__ w2, const float* __restrict__ w3,
               __nv_bfloat16* __restrict__ HH, __nv_bfloat16* __restrict__ HL,
               __nv_bfloat16* __restrict__ WH, __nv_bfloat16* __restrict__ WL)
{
    const int y = blockIdx.y;
    const int i = blockIdx.x * blockDim.x + threadIdx.x;
    const float* x;
    __nv_bfloat16 *h, *l;
    int n4;
    if (y == 4) {
        n4 = NTOK * DMODEL / 4;
        x = hid; h = HH; l = HL;
    } else {
        n4 = DMODEL * DMODEL / 4;
        x = (y == 0) ? w0 : (y == 1) ? w1 : (y == 2) ? w2 : w3;
        h = WH + (size_t)y * DMODEL * DMODEL;
        l = WL + (size_t)y * DMODEL * DMODEL;
    }
    if (i >= n4) return;
    float4 v = ((const float4*)x)[i];
    uint2 ph, pl;
    split_hilo2(v.x, v.y, ph.x, pl.x);
    split_hilo2(v.z, v.w, ph.y, pl.y);
    ((uint2*)h)[i] = ph;
    ((uint2*)l)[i] = pl;
}

// ---------------------------------------------------------------------------
// mma.sync m16n8k16 bf16 (f32 accumulate)
// ---------------------------------------------------------------------------
__device__ __forceinline__ void mma_bf16(float* c, const unsigned* a, const unsigned* b)
{
    asm volatile(
        "mma.sync.aligned.m16n8k16.row.col.f32.bf16.bf16.f32 "
        "{%0,%1,%2,%3},{%4,%5,%6,%7},{%8,%9},{%0,%1,%2,%3};"
        : "+f"(c[0]), "+f"(c[1]), "+f"(c[2]), "+f"(c[3])
        : "r"(a[0]), "r"(a[1]), "r"(a[2]), "r"(a[3]),
          "r"(b[0]), "r"(b[1]));
}

// ---------------------------------------------------------------------------
// GEMM core: 3-stage cp.async pipeline, ONE __syncthreads per iteration,
// hi|lo fused 128B rows with Swizzle<3,4,3> (chunk' = chunk ^ (row&7)).
// Row layout: cols [0,32) = hi elems, [32,64) = lo elems (chunks 0-3 / 4-7).
// ---------------------------------------------------------------------------
struct GemmSmem {
    __nv_bfloat16 A[128][64];   // 128B rows, swizzled 16B chunks
    __nv_bfloat16 W[128][64];
};
#define GEMM_STAGES 3
#define GEMM_SMEM_BYTES (GEMM_STAGES * (int)sizeof(GemmSmem))   // 98304

__device__ __forceinline__ void gemm_load_stage(
    GemmSmem& sm, const __nv_bfloat16* __restrict__ Ah, const __nv_bfloat16* __restrict__ Al,
    const __nv_bfloat16* __restrict__ Wh, const __nv_bfloat16* __restrict__ Wl,
    int bm, int bn, int k0, int tid)
{
    char* aBase = (char*)&sm.A[0][0];
    char* wBase = (char*)&sm.W[0][0];
#pragma unroll
    for (int it = 0; it < 4; it++) {
        int idx = tid + it * 256;          // 0..1023
        int row = idx >> 3, c = idx & 7;
        unsigned sw = (unsigned)(row * 128 + ((c ^ (row & 7)) << 4));
        const __nv_bfloat16* srcA = (c < 4)
            ? &Ah[(size_t)(bm + row) * DMODEL + k0 + c * 8]
            : &Al[(size_t)(bm + row) * DMODEL + k0 + (c - 4) * 8];
        const __nv_bfloat16* srcW = (c < 4)
            ? &Wh[(size_t)(bn + row) * DMODEL + k0 + c * 8]
            : &Wl[(size_t)(bn + row) * DMODEL + k0 + (c - 4) * 8];
        cp16(aBase + sw, srcA);
        cp16(wBase + sw, srcW);
    }
}

__device__ __forceinline__ void gemm_tile(
    GemmSmem* bufs, const __nv_bfloat16* __restrict__ Ah, const __nv_bfloat16* __restrict__ Al,
    const __nv_bfloat16* __restrict__ Wh, const __nv_bfloat16* __restrict__ Wl,
    int bm, int bn, float c[16][4])
{
    const int tid  = threadIdx.x;
    const int lane = tid & 31;
    const int w    = tid >> 5;
    const int wm   = w >> 2;
    const int wn   = w & 3;
    const int NKT  = DMODEL / 32;   // 24

    // ldmatrix per-lane row/chunk mapping (proven R12 fragment layout)
    const int rA = (lane & 7) + ((lane >> 3) & 1) * 8;   // A: row in 16-row tile
    const int cA = (lane >> 4) & 1;                      // A: 16B chunk offset
    const int rB = (lane & 7) + ((lane >> 4) & 1) * 8;   // W: row in 16-row tile
    const int cB = (lane >> 3) & 1;
    const int sw = lane & 7;                             // swizzle key (= row&7)

#pragma unroll
    for (int i = 0; i < 16; i++)
#pragma unroll
        for (int j = 0; j < 4; j++) c[i][j] = 0.f;

    gemm_load_stage(bufs[0], Ah, Al, Wh, Wl, bm, bn, 0, tid);
    CP_COMMIT();
    gemm_load_stage(bufs[1], Ah, Al, Wh, Wl, bm, bn, 32, tid);
    CP_COMMIT();

    for (int kt = 0; kt < NKT; kt++) {
        if (kt + 1 < NKT) { CP_WAIT1(); } else { CP_WAIT0(); }
        __syncthreads();   // single barrier per iteration (3-stage WAR-safe)

        GemmSmem& sm = bufs[kt % 3];
        const unsigned aRow = smem_u32(&sm.A[0][0]) + (unsigned)((wm * 64 + rA) * 128);
        const unsigned wRow = smem_u32(&sm.W[0][0]) + (unsigned)((wn * 32 + rB) * 128);

#pragma unroll
        for (int kf = 0; kf < 2; kf++) {
            const unsigned cAh = (unsigned)(((kf * 2 + cA) ^ sw) << 4);
            const unsigned cAl = (unsigned)(((4 + kf * 2 + cA) ^ sw) << 4);
            const unsigned cWh = (unsigned)(((kf * 2 + cB) ^ sw) << 4);
            const unsigned cWl = (unsigned)(((4 + kf * 2 + cB) ^ sw) << 4);
            unsigned ah[4][4], al[4][4];
#pragma unroll
            for (int mf = 0; mf < 4; mf++) {
                ldsm_x4(ah[mf], aRow + (unsigned)(mf * 16 * 128) + cAh);
                ldsm_x4(al[mf], aRow + (unsigned)(mf * 16 * 128) + cAl);
            }
            unsigned wh_[2][4], wl_[2][4];
#pragma unroll
            for (int p = 0; p < 2; p++) {
                ldsm_x4(wh_[p], wRow + (unsigned)(p * 16 * 128) + cWh);
                ldsm_x4(wl_[p], wRow + (unsigned)(p * 16 * 128) + cWl);
            }
#pragma unroll
            for (int mf = 0; mf < 4; mf++)
#pragma unroll
                for (int nf = 0; nf < 4; nf++) {
                    const unsigned* bh = &wh_[nf >> 1][(nf & 1) * 2];
                    const unsigned* bl = &wl_[nf >> 1][(nf & 1) * 2];
                    mma_bf16(c[mf * 4 + nf], ah[mf], bh);
                    mma_bf16(c[mf * 4 + nf], ah[mf], bl);
                    mma_bf16(c[mf * 4 + nf], al[mf], bh);
                }
        }

        if (kt + 2 < NKT) {
            gemm_load_stage(bufs[(kt + 2) % 3], Ah, Al, Wh, Wl, bm, bn, (kt + 2) * 32, tid);
            CP_COMMIT();
        }
    }
}

// ---------------------------------------------------------------------------
// Fused QKV projection: grid.z = 0(Q),1(K),2(V). Q pre-scaled by 0.125*log2(e).
// ---------------------------------------------------------------------------
__global__ void __launch_bounds__(256)
qkv_gemm_kernel(const __nv_bfloat16* __restrict__ Ah, const __nv_bfloat16* __restrict__ Al,
                const __nv_bfloat16* __restrict__ WhB, const __nv_bfloat16* __restrict__ WlB,
                const float* __restrict__ bq, const float* __restrict__ bk,
                const float* __restrict__ bv,
                __nv_bfloat16* __restrict__ QH, __nv_bfloat16* __restrict__ QL,
                __nv_bfloat16* __restrict__ KH, __nv_bfloat16* __restrict__ KL,
                __nv_bfloat16* __restrict__ VH, __nv_bfloat16* __restrict__ VL)
{
    extern __shared__ char smem_raw[];
    GemmSmem* bufs = (GemmSmem*)smem_raw;

    const int z = blockIdx.z;
    const __nv_bfloat16* Wh = WhB + (size_t)z * DMODEL * DMODEL;
    const __nv_bfloat16* Wl = WlB + (size_t)z * DMODEL * DMODEL;
    const float* bias = (z == 0) ? bq : (z == 1) ? bk : bv;
    const float scale = (z == 0) ? (0.125f * LOG2E) : 1.0f;
    __nv_bfloat16* CH = (z == 0) ? QH : (z == 1) ? KH : VH;
    __nv_bfloat16* CL = (z == 0) ? QL : (z == 1) ? KL : VL;

    const int bm = blockIdx.y * 128;
    const int bn = blockIdx.x * 128;
    float c[16][4];
    gemm_tile(bufs, Ah, Al, Wh, Wl, bm, bn, c);

    const int tid  = threadIdx.x;
    const int lane = tid & 31;
    const int w    = tid >> 5;
    const int g    = lane >> 2;
    const int t2   = (lane & 3) * 2;
    const int wm   = w >> 2;
    const int wn   = w & 3;

#pragma unroll
    for (int mf = 0; mf < 4; mf++) {
#pragma unroll
        for (int nf = 0; nf < 4; nf++) {
            const int colb = bn + wn * 32 + nf * 8 + t2;
            const float b0 = bias[colb], b1 = bias[colb + 1];
            float v[4] = { (c[mf * 4 + nf][0] + b0) * scale, (c[mf * 4 + nf][1] + b1) * scale,
                           (c[mf * 4 + nf][2] + b0) * scale, (c[mf * 4 + nf][3] + b1) * scale };
#pragma unroll
            for (int half = 0; half < 2; half++) {
                const int m = bm + wm * 64 + mf * 16 + g + half * 8;
                const float x0 = v[half * 2], x1 = v[half * 2 + 1];
                const int b = m >> 11;
                const int s = m & 2047;
                const int h = colb >> 6;
                const int d = colb & 63;
                unsigned hi, lo;
                split_hilo2(x0, x1, hi, lo);
                size_t idx = (((size_t)b * NHEAD + h) * S_LEN + s) * HDIM + d;
                *(unsigned*)&CH[idx] = hi;
                *(unsigned*)&CL[idx] = lo;
            }
        }
    }
}

// ---------------------------------------------------------------------------
// Output projection: plain fp32 [m,n]
// ---------------------------------------------------------------------------
__global__ void __launch_bounds__(256)
out_gemm_kernel(const __nv_bfloat16* __restrict__ Ah, const __nv_bfloat16* __restrict__ Al,
                const __nv_bfloat16* __restrict__ Wh, const __nv_bfloat16* __restrict__ Wl,
                const float* __restrict__ bias, float* __restrict__ Cf)
{
    extern __shared__ char smem_raw[];
    GemmSmem* bufs = (GemmSmem*)smem_raw;

    const int bm = blockIdx.y * 128;
    const int bn = blockIdx.x * 128;
    float c[16][4];
    gemm_tile(bufs, Ah, Al, Wh, Wl, bm, bn, c);

    const int tid  = threadIdx.x;
    const int lane = tid & 31;
    const int w    = tid >> 5;
    const int g    = lane >> 2;
    const int t2   = (lane & 3) * 2;
    const int wm   = w >> 2;
    const int wn   = w & 3;

#pragma unroll
    for (int mf = 0; mf < 4; mf++)
#pragma unroll
        for (int nf = 0; nf < 4; nf++) {
            const int colb = bn + wn * 32 + nf * 8 + t2;
            const float b0 = bias[colb], b1 = bias[colb + 1];
#pragma unroll
            for (int half = 0; half < 2; half++) {
                const int m = bm + wm * 64 + mf * 16 + g + half * 8;
                float2 p = { c[mf * 4 + nf][half * 2] + b0,
                             c[mf * 4 + nf][half * 2 + 1] + b1 };
                *(float2*)&Cf[(size_t)m * DMODEL + colb] = p;
            }
        }
}

#define MASKVAL (-1e30f)

// ---------------------------------------------------------------------------
// Flash attention (R16-proven): 32 q-rows per warp, 32-key tiles, exp2,
// V via ldmatrix.trans on [key][d] tiles. grid (S/128, H, B), 128 threads.
// ---------------------------------------------------------------------------
#define KT_KEYS 32
struct FlashSmem {
    __nv_bfloat16 kh[KT_KEYS][72];
    __nv_bfloat16 kl[KT_KEYS][72];
    __nv_bfloat16 vh[KT_KEYS][72];
    __nv_bfloat16 vl[KT_KEYS][72];
    unsigned m32[128];
};
#define FLASH_SMEM_BYTES (2 * (int)sizeof(FlashSmem))

__global__ void __launch_bounds__(128)
flash_mma_kernel(const __nv_bfloat16* __restrict__ qh, const __nv_bfloat16* __restrict__ ql,
                 const __nv_bfloat16* __restrict__ kh, const __nv_bfloat16* __restrict__ kl,
                 const __nv_bfloat16* __restrict__ vh, const __nv_bfloat16* __restrict__ vl,
                 const unsigned* __restrict__ mbits,
                 __nv_bfloat16* __restrict__ ch, __nv_bfloat16* __restrict__ cl)
{
    extern __shared__ char smem_raw[];
    FlashSmem* bufs = (FlashSmem*)smem_raw;

    const int tid  = threadIdx.x;
    const int w    = tid >> 5;
    const int lane = tid & 31;
    const int g    = lane >> 2;
    const int t2   = (lane & 3) * 2;
    const int qt = blockIdx.x, h = blockIdx.y, b = blockIdx.z;
    const int qbase = qt * 128;
    const int wq = w * 32;

    const size_t bh   = (size_t)(b * NHEAD + h);
    const size_t kvb  = bh * S_LEN * HDIM;
    const size_t mb32 = ((size_t)h * S_LEN + qbase) * (S_LEN / 32);
    const int NT = S_LEN / KT_KEYS;   // 64

    const unsigned lbK = (unsigned)(((lane & 7) + ((lane >> 4) & 1) * 8) * 144
                                    + ((lane >> 3) & 1) * 16);
    const unsigned lbVt = (unsigned)(((lane & 7) + ((lane >> 3) & 1) * 8) * 144
                                     + (lane >> 4) * 16);

    auto load_stage = [&](int buf, int kt) {
        FlashSmem& sm = bufs[buf];
#pragma unroll
        for (int it = 0; it < 2; it++) {
            int fid = tid + it * 128;
            int krow = fid >> 3, kcc = (fid & 7) * 8;
            cp16(&sm.kh[krow][kcc], &kh[kvb + (size_t)(kt * KT_KEYS + krow) * HDIM + kcc]);
            cp16(&sm.kl[krow][kcc], &kl[kvb + (size_t)(kt * KT_KEYS + krow) * HDIM + kcc]);
            cp16(&sm.vh[krow][kcc], &vh[kvb + (size_t)(kt * KT_KEYS + krow) * HDIM + kcc]);
            cp16(&sm.vl[krow][kcc], &vl[kvb + (size_t)(kt * KT_KEYS + krow) * HDIM + kcc]);
        }
        cp4(&sm.m32[tid], &mbits[mb32 + (size_t)tid * (S_LEN / 32) + kt]);
    };

    unsigned qfh[2][4][4], qfl[2][4][4];
#pragma unroll
    for (int mf = 0; mf < 2; mf++) {
        const size_t r0 = (size_t)(qbase + wq + mf * 16 + g) * HDIM;
        const size_t r1 = r0 + 8 * HDIM;
        const __nv_bfloat16* ph = qh + kvb;
        const __nv_bfloat16* pl = ql + kvb;
#pragma unroll
        for (int kf = 0; kf < 4; kf++) {
            int c0 = kf * 16 + t2, c1 = c0 + 8;
            qfh[mf][kf][0] = *(const unsigned*)&ph[r0 + c0];
            qfh[mf][kf][1] = *(const unsigned*)&ph[r1 + c0];
            qfh[mf][kf][2] = *(const unsigned*)&ph[r0 + c1];
            qfh[mf][kf][3] = *(const unsigned*)&ph[r1 + c1];
            qfl[mf][kf][0] = *(const unsigned*)&pl[r0 + c0];
            qfl[mf][kf][1] = *(const unsigned*)&pl[r1 + c0];
            qfl[mf][kf][2] = *(const unsigned*)&pl[r0 + c1];
            qfl[mf][kf][3] = *(const unsigned*)&pl[r1 + c1];
        }
    }

    float o[2][8][4];
#pragma unroll
    for (int mf = 0; mf < 2; mf++)
#pragma unroll
        for (int dt = 0; dt < 8; dt++)
#pragma unroll
            for (int i = 0; i < 4; i++) o[mf][dt][i] = 0.f;
    float lsum[2][2] = { {0.f, 0.f}, {0.f, 0.f} };

    load_stage(0, 0);
    CP_COMMIT();

    for (int kt = 0; kt < NT; kt++) {
        if (kt + 1 < NT) {
            load_stage((kt + 1) & 1, kt + 1);
            CP_COMMIT();
            CP_WAIT1();
        } else {
            CP_WAIT0();
        }
        __syncthreads();
        FlashSmem& sm = bufs[kt & 1];
        const unsigned khb = smem_u32(&sm.kh[0][0]) + lbK;
        const unsigned klb = smem_u32(&sm.kl[0][0]) + lbK;
        const unsigned vhb = smem_u32(&sm.vh[0][0]) + lbVt;
        const unsigned vlb = smem_u32(&sm.vl[0][0]) + lbVt;

        // ---- S = Q K^T ----
        float sacc[2][4][4];
#pragma unroll
        for (int mf = 0; mf < 2; mf++)
#pragma unroll
            for (int nt = 0; nt < 4; nt++)
#pragma unroll
                for (int i = 0; i < 4; i++) sacc[mf][nt][i] = 0.f;

#pragma unroll
        for (int kf = 0; kf < 4; kf++) {
#pragma unroll
            for (int p = 0; p < 2; p++) {
                unsigned bh4[4], bl4[4];
                ldsm_x4(bh4, khb + p * (16 * 144) + kf * 32);
                ldsm_x4(bl4, klb + p * (16 * 144) + kf * 32);
#pragma unroll
                for (int mf = 0; mf < 2; mf++) {
                    mma_bf16(sacc[mf][2 * p],     qfh[mf][kf], bh4 + 0);
                    mma_bf16(sacc[mf][2 * p],     qfh[mf][kf], bl4 + 0);
                    mma_bf16(sacc[mf][2 * p],     qfl[mf][kf], bh4 + 0);
                    mma_bf16(sacc[mf][2 * p + 1], qfh[mf][kf], bh4 + 2);
                    mma_bf16(sacc[mf][2 * p + 1], qfh[mf][kf], bl4 + 2);
                    mma_bf16(sacc[mf][2 * p + 1], qfl[mf][kf], bh4 + 2);
                }
            }
        }

        // ---- mask + p = exp2(s) + hi/lo split ----
        unsigned pfh[2][4][2], pfl[2][4][2];
#pragma unroll
        for (int mf = 0; mf < 2; mf++) {
            const unsigned w0 = sm.m32[wq + mf * 16 + g] >> t2;
            const unsigned w1 = sm.m32[wq + mf * 16 + 8 + g] >> t2;
#pragma unroll
            for (int nt = 0; nt < 4; nt++) {
                unsigned b0 = w0 >> (nt * 8);
                unsigned b1 = w1 >> (nt * 8);
                float s0 = (b0 & 1u) ? sacc[mf][nt][0] : MASKVAL;
                float s1 = (b0 & 2u) ? sacc[mf][nt][1] : MASKVAL;
                float s2 = (b1 & 1u) ? sacc[mf][nt][2] : MASKVAL;
                float s3 = (b1 & 2u) ? sacc[mf][nt][3] : MASKVAL;
                float p0 = exp2f(s0);
                float p1 = exp2f(s1);
                float p2 = exp2f(s2);
                float p3 = exp2f(s3);
                lsum[mf][0] += p0 + p1;
                lsum[mf][1] += p2 + p3;
                split_hilo2(p0, p1, pfh[mf][nt][0], pfl[mf][nt][0]);
                split_hilo2(p2, p3, pfh[mf][nt][1], pfl[mf][nt][1]);
            }
        }

        // ---- O += P V (trans-loaded V B-frags) ----
#pragma unroll
        for (int kc = 0; kc < 2; kc++) {
#pragma unroll
            for (int dg = 0; dg < 4; dg++) {
                unsigned bh4[4], bl4[4];
                ldsm_x4_t(bh4, vhb + kc * (16 * 144) + dg * 32);
                ldsm_x4_t(bl4, vlb + kc * (16 * 144) + dg * 32);
#pragma unroll
                for (int mf = 0; mf < 2; mf++) {
                    unsigned aph[4] = { pfh[mf][2 * kc][0], pfh[mf][2 * kc][1],
                                        pfh[mf][2 * kc + 1][0], pfh[mf][2 * kc + 1][1] };
                    unsigned apl[4] = { pfl[mf][2 * kc][0], pfl[mf][2 * kc][1],
                                        pfl[mf][2 * kc + 1][0], pfl[mf][2 * kc + 1][1] };
                    mma_bf16(o[mf][2 * dg],     aph, bh4 + 0);
                    mma_bf16(o[mf][2 * dg],     aph, bl4 + 0);
                    mma_bf16(o[mf][2 * dg],     apl, bh4 + 0);
                    mma_bf16(o[mf][2 * dg + 1], aph, bh4 + 2);
                    mma_bf16(o[mf][2 * dg + 1], aph, bl4 + 2);
                    mma_bf16(o[mf][2 * dg + 1], apl, bh4 + 2);
                }
            }
        }
        __syncthreads();
    }

#pragma unroll
    for (int mf = 0; mf < 2; mf++) {
        float l0 = lsum[mf][0], l1 = lsum[mf][1];
        l0 += __shfl_xor_sync(0xffffffffu, l0, 1);
        l0 += __shfl_xor_sync(0xffffffffu, l0, 2);
        l1 += __shfl_xor_sync(0xffffffffu, l1, 1);
        l1 += __shfl_xor_sync(0xffffffffu, l1, 2);
        const float rl0 = (l0 > 0.f) ? (1.f / l0) : 0.f;
        const float rl1 = (l1 > 0.f) ? (1.f / l1) : 0.f;

        const int qr0 = qbase + wq + mf * 16 + g;
        const size_t o0 = ((size_t)b * S_LEN + qr0) * DMODEL + h * HDIM;
        const size_t o1 = o0 + (size_t)8 * DMODEL;
#pragma unroll
        for (int dt = 0; dt < 8; dt++) {
            unsigned hiA, loA, hiB, loB;
            split_hilo2(o[mf][dt][0] * rl0, o[mf][dt][1] * rl0, hiA, loA);
            split_hilo2(o[mf][dt][2] * rl1, o[mf][dt][3] * rl1, hiB, loB);
            *(unsigned*)&ch[o0 + dt * 8 + t2] = hiA;
            *(unsigned*)&cl[o0 + dt * 8 + t2] = loA;
            *(unsigned*)&ch[o1 + dt * 8 + t2] = hiB;
            *(unsigned*)&cl[o1 + dt * 8 + t2] = loB;
        }
    }
}

// ---------------------------------------------------------------------------
extern "C" void kernel_launch(void* const* d_in, const int* in_sizes, int n_in,
                              void* d_out, int out_size)
{
    const float* hidden = (const float*)d_in[0];
    const void*  mask_raw = d_in[1];
    const float* q_w = (const float*)d_in[2];
    const float* q_b = (const float*)d_in[3];
    const float* k_w = (const float*)d_in[4];
    const float* k_b = (const float*)d_in[5];
    const float* v_w = (const float*)d_in[6];
    const float* v_b = (const float*)d_in[7];
    const float* out_w = (const float*)d_in[8];
    const float* out_b = (const float*)d_in[9];
    float* out = (float*)d_out;

    __nv_bfloat16 *ghh, *ghl, *gwh, *gwl, *gqh, *gql, *gkh, *gkl, *gvh, *gvl, *gch, *gcl;
    unsigned* gmb;
    cudaGetSymbolAddress((void**)&ghh, g_hh);
    cudaGetSymbolAddress((void**)&ghl, g_hl);
    cudaGetSymbolAddress((void**)&gwh, g_wh);
    cudaGetSymbolAddress((void**)&gwl, g_wl);
    cudaGetSymbolAddress((void**)&gqh, g_qh);
    cudaGetSymbolAddress((void**)&gql, g_ql);
    cudaGetSymbolAddress((void**)&gkh, g_kh);
    cudaGetSymbolAddress((void**)&gkl, g_kl);
    cudaGetSymbolAddress((void**)&gvh, g_vh);
    cudaGetSymbolAddress((void**)&gvl, g_vl);
    cudaGetSymbolAddress((void**)&gch, g_ch);
    cudaGetSymbolAddress((void**)&gcl, g_cl);
    cudaGetSymbolAddress((void**)&gmb, g_maskbits);

    static bool init_done = false;
    static cudaStream_t s2;
    static cudaEvent_t evFork, evJoin;
    if (!init_done) {
        cudaFuncSetAttribute(qkv_gemm_kernel,
            cudaFuncAttributeMaxDynamicSharedMemorySize, GEMM_SMEM_BYTES);
        cudaFuncSetAttribute(out_gemm_kernel,
            cudaFuncAttributeMaxDynamicSharedMemorySize, GEMM_SMEM_BYTES);
        cudaFuncSetAttribute(flash_mma_kernel,
            cudaFuncAttributeMaxDynamicSharedMemorySize, FLASH_SMEM_BYTES);
        cudaStreamCreateWithFlags(&s2, cudaStreamNonBlocking);
        cudaEventCreateWithFlags(&evFork, cudaEventDisableTiming);
        cudaEventCreateWithFlags(&evJoin, cudaEventDisableTiming);
        init_done = true;
    }

    // (1) mask dtype detection (main stream)
    detect_mask_kernel<<<1, 256>>>((const unsigned char*)mask_raw);

    // fork: mask -> bitmask on side stream (overlaps cvt + QKV GEMM)
    cudaEventRecord(evFork, 0);
    cudaStreamWaitEvent(s2, evFork, 0);
    convert_maskbits_kernel<<<(MASK_N / 32 + 255) / 256, 256, 0, s2>>>(mask_raw, gmb);
    cudaEventRecord(evJoin, s2);

    // (2) fused hidden + weights hi/lo conversion (main stream)
    const int nh4 = NTOK * DMODEL / 4;
    dim3 cvtGrid((nh4 + 255) / 256, 5);
    cvt_all_kernel<<<cvtGrid, 256>>>(hidden, q_w, k_w, v_w, out_w, ghh, ghl, gwh, gwl);

    // (3) fused QKV projections (3-stage pipeline)
    dim3 qkvGrid(DMODEL / 128, NTOK / 128, 3);
    qkv_gemm_kernel<<<qkvGrid, 256, GEMM_SMEM_BYTES>>>(ghh, ghl, gwh, gwl,
        q_b, k_b, v_b, gqh, gql, gkh, gkl, gvh, gvl);

    // join: bitmask must be ready before flash
    cudaStreamWaitEvent(0, evJoin, 0);

    // (4) flash attention
    dim3 flashGrid(S_LEN / 128, NHEAD, BATCH);
    flash_mma_kernel<<<flashGrid, 128, FLASH_SMEM_BYTES>>>(gqh, gql, gkh, gkl, gvh, gvl,
        gmb, gch, gcl);

    // (5) output projection
    dim3 gemmGrid(DMODEL / 128, NTOK / 128);
    out_gemm_kernel<<<gemmGrid, 256, GEMM_SMEM_BYTES>>>(gch, gcl,
        gwh + 3 * (size_t)DMODEL * DMODEL, gwl + 3 * (size_t)DMODEL * DMODEL,
        out_b, out);
}